// round 9
// baseline (speedup 1.0000x reference)
#include <cuda_runtime.h>
#include <cuda_bf16.h>
#include <cstdint>
#include <cstddef>

#define NBR 8
#define MROWS 16384
#define BN_EPS 1e-5f

__device__ __align__(256) float g_bufA[(size_t)NBR * MROWS * 512];
__device__ __align__(256) float g_bufB[(size_t)NBR * MROWS * 512];
__device__ __align__(256) float g_h4 [(size_t)NBR * MROWS * 64];
__device__ __align__(256) float g_t1 [(size_t)NBR * MROWS * 64];
__device__ __align__(256) float g_t2 [(size_t)NBR * MROWS * 128];
__device__ __align__(256) float g_t3 [(size_t)NBR * MROWS * 128];
__device__ float g_psum [NBR * 512 * 128];
__device__ float g_psq  [NBR * 512 * 128];
__device__ float g_scale[6 * NBR * 512];
__device__ float g_shift[6 * NBR * 512];
__device__ __align__(16) __nv_bfloat16 g_Ah[(size_t)NBR * MROWS * 512];
__device__ __align__(16) __nv_bfloat16 g_Al[(size_t)NBR * MROWS * 512];
__device__ __align__(16) __nv_bfloat16 g_Xh[(size_t)MROWS * 256];
__device__ __align__(16) __nv_bfloat16 g_Xl[(size_t)MROWS * 256];
__device__ __align__(16) __nv_bfloat16 g_W1h[NBR * 512 * 256];
__device__ __align__(16) __nv_bfloat16 g_W1l[NBR * 512 * 256];
__device__ __align__(16) __nv_bfloat16 g_W2h[NBR * 512 * 512];
__device__ __align__(16) __nv_bfloat16 g_W2l[NBR * 512 * 512];
__device__ __align__(16) __nv_bfloat16 g_W3h[NBR * 512 * 512];
__device__ __align__(16) __nv_bfloat16 g_W3l[NBR * 512 * 512];
__device__ __align__(16) __nv_bfloat16 g_W4h[NBR * 128 * 512];
__device__ __align__(16) __nv_bfloat16 g_W4l[NBR * 128 * 512];

__device__ __forceinline__ uint32_t smem_u32(const void* p) {
    uint32_t a;
    asm("{ .reg .u64 t; cvta.to.shared.u64 t, %1; cvt.u32.u64 %0, t; }" : "=r"(a) : "l"(p));
    return a;
}
__device__ __forceinline__ void stc_f32(uint32_t sa, uint32_t rank, float v) {
    uint32_t r;
    asm volatile("mapa.shared::cluster.u32 %0, %1, %2;" : "=r"(r) : "r"(sa), "r"(rank));
    asm volatile("st.shared::cluster.f32 [%0], %1;" :: "r"(r), "f"(v) : "memory");
}
__device__ __forceinline__ void stc_u32(uint32_t sa, uint32_t rank, uint32_t v) {
    uint32_t r;
    asm volatile("mapa.shared::cluster.u32 %0, %1, %2;" : "=r"(r) : "r"(sa), "r"(rank));
    asm volatile("st.shared::cluster.u32 [%0], %1;" :: "r"(r), "r"(v) : "memory");
}
__device__ __forceinline__ void cpa16(uint32_t d, const void* g) {
    asm volatile("cp.async.cg.shared.global [%0], [%1], 16;" :: "r"(d), "l"(g));
}
#define CP_COMMIT() asm volatile("cp.async.commit_group;")
#define CP_WAIT(N)  asm volatile("cp.async.wait_group %0;" :: "n"(N))
#define LDSM4(R, ADDR) \
    asm volatile("ldmatrix.sync.aligned.m8n8.x4.shared.b16 {%0,%1,%2,%3}, [%4];" \
        : "=r"((R)[0]), "=r"((R)[1]), "=r"((R)[2]), "=r"((R)[3]) : "r"(ADDR))
#define MMA16816(D, A, B0, B1) \
    asm volatile("mma.sync.aligned.m16n8k16.row.col.f32.bf16.bf16.f32 " \
        "{%0,%1,%2,%3}, {%4,%5,%6,%7}, {%8,%9}, {%0,%1,%2,%3};" \
        : "+f"((D)[0]), "+f"((D)[1]), "+f"((D)[2]), "+f"((D)[3]) \
        : "r"((A)[0]), "r"((A)[1]), "r"((A)[2]), "r"((A)[3]), "r"(B0), "r"(B1))

// ------------------------------ FPS (proven) --------------------------------
#define FPS_CL 4
__global__ void __cluster_dims__(FPS_CL,1,1) __launch_bounds__(512,1)
fps_kernel(const float* __restrict__ xpart, float* __restrict__ out)
{
    uint32_t rank; asm("mov.u32 %0, %%cluster_ctarank;" : "=r"(rank));
    int b = blockIdx.x / FPS_CL;
    const float* xp = xpart + (size_t)b * 32768 * 3;
    int tid = threadIdx.x, lane = tid & 31, warp = tid >> 5;
    int pbase = (int)rank * 8192;
    float px[16], py[16], pz[16], dd[16];
#pragma unroll
    for (int i = 0; i < 16; i++) {
        int p = pbase + tid + 512 * i;
        px[i] = xp[p*3]; py[i] = xp[p*3+1]; pz[i] = xp[p*3+2]; dd[i] = 1e10f;
    }
    __shared__ float wv_[16]; __shared__ int wi_[16];
    __shared__ float wx_[16], wy_[16], wz_[16];
    __shared__ float cval[2][FPS_CL]; __shared__ int cidx[2][FPS_CL];
    __shared__ float cxx[2][FPS_CL], cyy[2][FPS_CL], czz[2][FPS_CL];
    float curx = xp[0], cury = xp[1], curz = xp[2];
    float* orow = out + ((size_t)b * 2048 + 1024) * 3;
    if (rank == 0 && tid == 0) { orow[0]=curx; orow[1]=cury; orow[2]=curz; }

    for (int t = 1; t < 1024; t++) {
        float bv = -1.f; int bi = 0x7fffffff;
        float bx = 0.f, by = 0.f, bz = 0.f;
#pragma unroll
        for (int i = 0; i < 16; i++) {
            float dx = __fsub_rn(px[i], curx), dy = __fsub_rn(py[i], cury), dz = __fsub_rn(pz[i], curz);
            float d = __fadd_rn(__fadd_rn(__fmul_rn(dx,dx), __fmul_rn(dy,dy)), __fmul_rn(dz,dz));
            dd[i] = fminf(dd[i], d);
            int gi = pbase + tid + 512 * i;
            if (dd[i] > bv || (dd[i] == bv && gi < bi)) { bv=dd[i]; bi=gi; bx=px[i]; by=py[i]; bz=pz[i]; }
        }
#pragma unroll
        for (int s = 16; s > 0; s >>= 1) {
            float ov = __shfl_down_sync(0xffffffffu, bv, s);
            int   oi = __shfl_down_sync(0xffffffffu, bi, s);
            float ox = __shfl_down_sync(0xffffffffu, bx, s);
            float oy = __shfl_down_sync(0xffffffffu, by, s);
            float oz = __shfl_down_sync(0xffffffffu, bz, s);
            if (ov > bv || (ov == bv && oi < bi)) { bv=ov; bi=oi; bx=ox; by=oy; bz=oz; }
        }
        if (lane == 0) { wv_[warp]=bv; wi_[warp]=bi; wx_[warp]=bx; wy_[warp]=by; wz_[warp]=bz; }
        __syncthreads();
        int par = t & 1;
        if (warp == 0) {
            bv = (lane < 16) ? wv_[lane] : -1.f;
            bi = (lane < 16) ? wi_[lane] : 0x7fffffff;
            bx = (lane < 16) ? wx_[lane] : 0.f;
            by = (lane < 16) ? wy_[lane] : 0.f;
            bz = (lane < 16) ? wz_[lane] : 0.f;
#pragma unroll
            for (int s = 8; s > 0; s >>= 1) {
                float ov = __shfl_down_sync(0xffffffffu, bv, s);
                int   oi = __shfl_down_sync(0xffffffffu, bi, s);
                float ox = __shfl_down_sync(0xffffffffu, bx, s);
                float oy = __shfl_down_sync(0xffffffffu, by, s);
                float oz = __shfl_down_sync(0xffffffffu, bz, s);
                if (ov > bv || (ov == bv && oi < bi)) { bv=ov; bi=oi; bx=ox; by=oy; bz=oz; }
            }
            if (lane == 0) {
                for (uint32_t r = 0; r < FPS_CL; r++) {
                    stc_f32(smem_u32(&cval[par][rank]), r, bv);
                    stc_u32(smem_u32(&cidx[par][rank]), r, (uint32_t)bi);
                    stc_f32(smem_u32(&cxx[par][rank]), r, bx);
                    stc_f32(smem_u32(&cyy[par][rank]), r, by);
                    stc_f32(smem_u32(&czz[par][rank]), r, bz);
                }
            }
        }
        asm volatile("barrier.cluster.arrive.aligned;" ::: "memory");
        asm volatile("barrier.cluster.wait.aligned;" ::: "memory");
        float vv = cval[par][0]; int vi = cidx[par][0];
        float nx = cxx[par][0], ny = cyy[par][0], nz = czz[par][0];
#pragma unroll
        for (int r = 1; r < FPS_CL; r++) {
            float ov = cval[par][r]; int oi = cidx[par][r];
            if (ov > vv || (ov == vv && oi < vi)) { vv=ov; vi=oi; nx=cxx[par][r]; ny=cyy[par][r]; nz=czz[par][r]; }
        }
        curx = nx; cury = ny; curz = nz;
        if (rank == 0 && tid == 0) { orow[t*3]=nx; orow[t*3+1]=ny; orow[t*3+2]=nz; }
    }
}

// --------------------- vectorized conversion passes -------------------------
__device__ __forceinline__ void pack8(const float* v, uint4& H, uint4& L) {
    uint32_t h[4], l[4];
#pragma unroll
    for (int i = 0; i < 4; i++) {
        __nv_bfloat162 hh, ll;
        float x = v[2*i], y = v[2*i+1];
        hh.x = __float2bfloat16(x); hh.y = __float2bfloat16(y);
        ll.x = __float2bfloat16(x - __bfloat162float(hh.x));
        ll.y = __float2bfloat16(y - __bfloat162float(hh.y));
        h[i] = *reinterpret_cast<uint32_t*>(&hh);
        l[i] = *reinterpret_cast<uint32_t*>(&ll);
    }
    H = make_uint4(h[0], h[1], h[2], h[3]);
    L = make_uint4(l[0], l[1], l[2], l[3]);
}

// 8 floats per thread; nFloats must be divisible by 2048
__global__ void conv_plain_v(const float* __restrict__ S, __nv_bfloat16* __restrict__ H,
                             __nv_bfloat16* __restrict__ L)
{
    size_t p = ((size_t)blockIdx.x * 256 + threadIdx.x) * 8;
    float4 a = *(const float4*)(S + p);
    float4 b = *(const float4*)(S + p + 4);
    float v[8] = {a.x, a.y, a.z, a.w, b.x, b.y, b.z, b.w};
    uint4 Hh, Ll; pack8(v, Hh, Ll);
    *(uint4*)(H + p) = Hh; *(uint4*)(L + p) = Ll;
}
// mW4 [NBR][64][512] -> padded [NBR][128][512] (rows 64..127 zero)
__global__ void conv_w4_v(const float* __restrict__ S, __nv_bfloat16* __restrict__ H,
                          __nv_bfloat16* __restrict__ L)
{
    size_t p = ((size_t)blockIdx.x * 256 + threadIdx.x) * 8;
    int k = (int)(p & 511), n = (int)((p >> 9) & 127), z = (int)(p >> 16);
    float v[8] = {0.f, 0.f, 0.f, 0.f, 0.f, 0.f, 0.f, 0.f};
    if (n < 64) {
        const float* s = S + ((size_t)z * 64 + n) * 512 + k;
        float4 a = *(const float4*)(s);
        float4 b = *(const float4*)(s + 4);
        v[0]=a.x; v[1]=a.y; v[2]=a.z; v[3]=a.w; v[4]=b.x; v[5]=b.y; v[6]=b.z; v[7]=b.w;
    }
    uint4 Hh, Ll; pack8(v, Hh, Ll);
    *(uint4*)(H + p) = Hh; *(uint4*)(L + p) = Ll;
}
// BN+ReLU apply + split, 8 floats/thread, rows of 512 channels
__global__ void conv_bn_v(const float* __restrict__ raw, const float* __restrict__ sc,
                          const float* __restrict__ sh, __nv_bfloat16* __restrict__ H,
                          __nv_bfloat16* __restrict__ L)
{
    size_t p = ((size_t)blockIdx.x * 256 + threadIdx.x) * 8;
    int k = (int)(p & 511), z = (int)(p >> 23);   // p>>9 = row; row>>14 = z
    float4 a = *(const float4*)(raw + p);
    float4 b = *(const float4*)(raw + p + 4);
    const float* scz = sc + z * 512 + k;
    const float* shz = sh + z * 512 + k;
    float4 s0 = *(const float4*)(scz), s1 = *(const float4*)(scz + 4);
    float4 t0 = *(const float4*)(shz), t1 = *(const float4*)(shz + 4);
    float v[8];
    v[0] = fmaxf(fmaf(a.x, s0.x, t0.x), 0.f);
    v[1] = fmaxf(fmaf(a.y, s0.y, t0.y), 0.f);
    v[2] = fmaxf(fmaf(a.z, s0.z, t0.z), 0.f);
    v[3] = fmaxf(fmaf(a.w, s0.w, t0.w), 0.f);
    v[4] = fmaxf(fmaf(b.x, s1.x, t1.x), 0.f);
    v[5] = fmaxf(fmaf(b.y, s1.y, t1.y), 0.f);
    v[6] = fmaxf(fmaf(b.z, s1.z, t1.z), 0.f);
    v[7] = fmaxf(fmaf(b.w, s1.w, t1.w), 0.f);
    uint4 Hh, Ll; pack8(v, Hh, Ll);
    *(uint4*)(H + p) = Hh; *(uint4*)(L + p) = Ll;
}

// -------------- bf16-split tensor-core GEMM, cp.async, 2 CTAs/SM ----------
__global__ void __launch_bounds__(256, 2)
gemm_mma2(const __nv_bfloat16* __restrict__ Agh, const __nv_bfloat16* __restrict__ Agl,
          const __nv_bfloat16* __restrict__ Bgh, const __nv_bfloat16* __restrict__ Bgl,
          float* __restrict__ Call, float* __restrict__ psum, float* __restrict__ psq,
          int K, long aStride, long bStride, int Nout)
{
    extern __shared__ __align__(16) uint32_t sm[];
    int bx = blockIdx.x, by = blockIdx.y, z = blockIdx.z;
    int tid = threadIdx.x, lane = tid & 31, w = tid >> 5;
    int wm = w & 1, wn = w >> 1;
    int m0 = by * 128, n0 = bx * 128, KC = K >> 5;
    const __nv_bfloat16* Ah = Agh + (size_t)z * aStride;
    const __nv_bfloat16* Al = Agl + (size_t)z * aStride;
    const __nv_bfloat16* Bh = Bgh + (size_t)z * bStride;
    const __nv_bfloat16* Bl = Bgl + (size_t)z * bStride;
    uint32_t sbase = smem_u32(sm);

    int lr = tid >> 1, half = tid & 1;
    const __nv_bfloat16* Ar_h = Ah + (size_t)(m0 + lr) * K + half * 16;
    const __nv_bfloat16* Ar_l = Al + (size_t)(m0 + lr) * K + half * 16;
    const __nv_bfloat16* Br_h = Bh + (size_t)(n0 + lr) * K + half * 16;
    const __nv_bfloat16* Br_l = Bl + (size_t)(n0 + lr) * K + half * 16;
    uint32_t drow = lr * 80 + half * 32;

    auto fill = [&](int kc, int s) {
        uint32_t st = sbase + s * 40960;
        int go = kc * 32;
        cpa16(st + drow,                Ar_h + go);
        cpa16(st + drow + 16,           Ar_h + go + 8);
        cpa16(st + 10240 + drow,        Ar_l + go);
        cpa16(st + 10240 + drow + 16,   Ar_l + go + 8);
        cpa16(st + 20480 + drow,        Br_h + go);
        cpa16(st + 20480 + drow + 16,   Br_h + go + 8);
        cpa16(st + 30720 + drow,        Br_l + go);
        cpa16(st + 30720 + drow + 16,   Br_l + go + 8);
    };

    float acc[4][4][4];
#pragma unroll
    for (int i = 0; i < 4; i++)
#pragma unroll
        for (int j = 0; j < 4; j++)
#pragma unroll
            for (int e = 0; e < 4; e++) acc[i][j][e] = 0.f;

    fill(0, 0); CP_COMMIT();
    fill(1, 1); CP_COMMIT();

    int arow = lane & 15, kh = (lane >> 4) * 8;
    int bn_ = ((lane >> 4) & 1) * 8 + (lane & 7), bk = ((lane >> 3) & 1) * 8;

    for (int kc = 0; kc < KC; kc++) {
        int s = kc & 1;
        if (kc + 1 < KC) { CP_WAIT(1); } else { CP_WAIT(0); }
        __syncthreads();
        uint32_t abase = sbase + s * 40960 + (wm * 64) * 80;
        uint32_t bbase = sbase + s * 40960 + 20480 + (wn * 32) * 80;
#pragma unroll
        for (int ks = 0; ks < 2; ks++) {
            uint32_t bh[2][4], blr[2][4];
#pragma unroll
            for (int g = 0; g < 2; g++) {
                uint32_t bd = bbase + (g*16 + bn_) * 80 + (ks*16 + bk) * 2;
                LDSM4(bh[g], bd);
                LDSM4(blr[g], bd + 10240);
            }
#pragma unroll
            for (int mt = 0; mt < 4; mt++) {
                uint32_t ah[4], alr[4];
                uint32_t ad = abase + (mt*16 + arow) * 80 + (ks*16 + kh) * 2;
                LDSM4(ah, ad);
                LDSM4(alr, ad + 10240);
#pragma unroll
                for (int nt = 0; nt < 4; nt++) {
                    int g = nt >> 1, p = (nt & 1) * 2;
                    MMA16816(acc[mt][nt], ah,  bh[g][p],  bh[g][p+1]);
                    MMA16816(acc[mt][nt], ah,  blr[g][p], blr[g][p+1]);
                    MMA16816(acc[mt][nt], alr, bh[g][p],  bh[g][p+1]);
                }
            }
        }
        __syncthreads();
        if (kc + 2 < KC) { fill(kc + 2, s); CP_COMMIT(); }
    }

    float* cs = (float*)sm;
#pragma unroll
    for (int mt = 0; mt < 4; mt++)
#pragma unroll
        for (int nt = 0; nt < 4; nt++) {
            int r = wm*64 + mt*16 + (lane >> 2);
            int c = wn*32 + nt*8 + (lane & 3) * 2;
            *(float2*)(cs + r*132 + c)     = make_float2(acc[mt][nt][0], acc[mt][nt][1]);
            *(float2*)(cs + (r+8)*132 + c) = make_float2(acc[mt][nt][2], acc[mt][nt][3]);
        }
    __syncthreads();
    if (tid < 128 && n0 + tid < Nout) {
        float s = 0.f, q = 0.f;
#pragma unroll 8
        for (int r = 0; r < 128; r++) { float v = cs[r*132 + tid]; s += v; q = fmaf(v, v, q); }
        size_t ch = (size_t)z * Nout + n0 + tid;
        psum[ch * 128 + by] = s; psq[ch * 128 + by] = q;
    }
    float* C = Call + (size_t)z * MROWS * Nout;
#pragma unroll
    for (int i = 0; i < 16; i++) {
        int lin = tid + 256 * i;
        int r = lin >> 5, c4 = (lin & 31) * 4;
        if (n0 + c4 < Nout) {
            float4 v = *(float4*)(cs + r*132 + c4);
            *(float4*)(C + (size_t)(m0 + r) * Nout + n0 + c4) = v;
        }
    }
}

// --------------------------- SIMT small GEMM (proven) -----------------------
template<int BN, int TN, bool HAS_T, bool HAS_S>
__global__ void __launch_bounds__(256)
gemm_bn(const float* __restrict__ Aall, const float* __restrict__ Wall, float* __restrict__ Call,
        const float* __restrict__ tsc, const float* __restrict__ tsh,
        float* __restrict__ psum, float* __restrict__ psq, int M, int N, int K, long aStride)
{
    constexpr int BM = 128, BK = 8, TM = 8;
    int z = blockIdx.z;
    const float* A = Aall + (size_t)z * (size_t)aStride;
    const float* W = Wall + (size_t)z * N * K;
    float* C = Call + (size_t)z * (size_t)M * N;
    const float* sc = HAS_T ? (tsc + z * K) : nullptr;
    const float* sh = HAS_T ? (tsh + z * K) : nullptr;
    __shared__ float As[BK][BM], Bs[BK][BN], red[16][BN];
    int t = threadIdx.x, m0 = blockIdx.y * BM, n0 = blockIdx.x * BN;
    int tcol = t & 15, trow = t >> 4;
    float acc[TM][TN];
#pragma unroll
    for (int i = 0; i < TM; i++)
#pragma unroll
        for (int j = 0; j < TN; j++) acc[i][j] = 0.f;
    int ar = t >> 1, ac4 = (t & 1) * 4;
    const float* Aload = A + (size_t)(m0 + ar) * K + ac4;
    for (int k0 = 0; k0 < K; k0 += BK) {
        float4 avv = *(const float4*)(Aload + k0);
        if (HAS_T) {
            int c = k0 + ac4;
            avv.x = fmaxf(fmaf(avv.x, sc[c],   sh[c]),   0.f);
            avv.y = fmaxf(fmaf(avv.y, sc[c+1], sh[c+1]), 0.f);
            avv.z = fmaxf(fmaf(avv.z, sc[c+2], sh[c+2]), 0.f);
            avv.w = fmaxf(fmaf(avv.w, sc[c+3], sh[c+3]), 0.f);
        }
        As[ac4][ar] = avv.x; As[ac4+1][ar] = avv.y; As[ac4+2][ar] = avv.z; As[ac4+3][ar] = avv.w;
        for (int e = t; e < BN * 2; e += 256) {
            int wr = e >> 1, wc = (e & 1) * 4;
            float4 wv = *(const float4*)(W + (size_t)(n0 + wr) * K + k0 + wc);
            Bs[wc][wr] = wv.x; Bs[wc+1][wr] = wv.y; Bs[wc+2][wr] = wv.z; Bs[wc+3][wr] = wv.w;
        }
        __syncthreads();
#pragma unroll
        for (int kk = 0; kk < BK; kk++) {
            float a[TM], bb[TN];
            const float4* A4 = (const float4*)(&As[kk][trow * TM]);
            float4 t0 = A4[0], t1 = A4[1];
            a[0]=t0.x; a[1]=t0.y; a[2]=t0.z; a[3]=t0.w; a[4]=t1.x; a[5]=t1.y; a[6]=t1.z; a[7]=t1.w;
            const float4* B4 = (const float4*)(&Bs[kk][tcol * TN]);
            float4 u0 = B4[0];
            bb[0]=u0.x; bb[1]=u0.y; bb[2]=u0.z; bb[3]=u0.w;
            if constexpr (TN == 8) { float4 u1 = B4[1]; bb[4]=u1.x; bb[5]=u1.y; bb[6]=u1.z; bb[7]=u1.w; }
#pragma unroll
            for (int i = 0; i < TM; i++)
#pragma unroll
                for (int j = 0; j < TN; j++) acc[i][j] = fmaf(a[i], bb[j], acc[i][j]);
        }
        __syncthreads();
    }
#pragma unroll
    for (int i = 0; i < TM; i++) {
        float* crow = C + (size_t)(m0 + trow * TM + i) * N + n0 + tcol * TN;
#pragma unroll
        for (int j = 0; j < TN; j += 4)
            *(float4*)(crow + j) = make_float4(acc[i][j], acc[i][j+1], acc[i][j+2], acc[i][j+3]);
    }
    if (HAS_S) {
        float cs2[TN], cq[TN];
#pragma unroll
        for (int j = 0; j < TN; j++) {
            cs2[j] = 0.f; cq[j] = 0.f;
#pragma unroll
            for (int i = 0; i < TM; i++) { cs2[j] += acc[i][j]; cq[j] = fmaf(acc[i][j], acc[i][j], cq[j]); }
        }
#pragma unroll
        for (int j = 0; j < TN; j++) red[trow][tcol * TN + j] = cs2[j];
        __syncthreads();
        for (int s = 8; s > 0; s >>= 1) {
            if (trow < s)
#pragma unroll
                for (int j = 0; j < TN; j++) red[trow][tcol*TN+j] += red[trow+s][tcol*TN+j];
            __syncthreads();
        }
        if (trow == 0)
#pragma unroll
            for (int j = 0; j < TN; j++)
                psum[(size_t)(z * N + n0 + tcol * TN + j) * 128 + blockIdx.y] = red[0][tcol*TN+j];
        __syncthreads();
#pragma unroll
        for (int j = 0; j < TN; j++) red[trow][tcol * TN + j] = cq[j];
        __syncthreads();
        for (int s = 8; s > 0; s >>= 1) {
            if (trow < s)
#pragma unroll
                for (int j = 0; j < TN; j++) red[trow][tcol*TN+j] += red[trow+s][tcol*TN+j];
            __syncthreads();
        }
        if (trow == 0)
#pragma unroll
            for (int j = 0; j < TN; j++)
                psq[(size_t)(z * N + n0 + tcol * TN + j) * 128 + blockIdx.y] = red[0][tcol*TN+j];
    }
}

__global__ void bn_finalize(const float* __restrict__ psum, const float* __restrict__ psq,
                            const float* __restrict__ gam, const float* __restrict__ bet,
                            float* __restrict__ sc, float* __restrict__ sh, int total)
{
    int i = blockIdx.x * blockDim.x + threadIdx.x;
    if (i >= total) return;
    float s = 0.f, q = 0.f;
    const float* ps = psum + (size_t)i * 128;
    const float* pq = psq + (size_t)i * 128;
#pragma unroll 8
    for (int k = 0; k < 128; k++) { s += ps[k]; q += pq[k]; }
    float mean = s * (1.f / 16384.f);
    float var = fmaf(-mean, mean, q * (1.f / 16384.f));
    float g = gam[i] * rsqrtf(var + BN_EPS);
    sc[i] = g; sh[i] = fmaf(-mean, g, bet[i]);
}

// ----------------------------- softmax/pool (proven) ------------------------
__global__ void __launch_bounds__(256, 1)
softmax_pts_kernel(const float* __restrict__ t3, const float* __restrict__ h4raw,
                   const float* __restrict__ scaleL, const float* __restrict__ shiftL,
                   const float* __restrict__ aW4, const float* __restrict__ ab4,
                   float* __restrict__ out)
{
    int b = blockIdx.x, n = blockIdx.y;
    extern __shared__ float base_sh[];
    __shared__ float w4[3][64], b4[3];
    int tid = threadIdx.x;
    if (tid < 192) w4[tid / 64][tid % 64] = aW4[n * 192 + tid];
    if (tid < 3) b4[tid] = ab4[n * 3 + tid];
    const float* sc = scaleL + n * 64;
    const float* sh = shiftL + n * 64;
    const float* h4b = h4raw + ((size_t)n * MROWS + b * 512) * 64;
    for (int i = tid; i < 512 * 64; i += 256) {
        int l = i >> 6, k = i & 63;
        base_sh[l * 65 + k] = fmaxf(fmaf(h4b[i], sc[k], sh[k]), 0.f);
    }
    __syncthreads();
    int lane = tid & 31, warp = tid >> 5;
    const float* t3b = t3 + ((size_t)n * MROWS + b * 512) * 128;
    float* orow = out + ((size_t)b * 2048 + n * 128) * 3;
    for (int c = 0; c < 16; c++) {
        int m = warp + c * 8;
        float v[16], mx = -1e30f;
#pragma unroll
        for (int i = 0; i < 16; i++) { v[i] = t3b[(size_t)(lane + 32*i) * 128 + m]; mx = fmaxf(mx, v[i]); }
#pragma unroll
        for (int s = 16; s > 0; s >>= 1) mx = fmaxf(mx, __shfl_xor_sync(0xffffffffu, mx, s));
        float sum = 0.f;
#pragma unroll
        for (int i = 0; i < 16; i++) { v[i] = expf(v[i] - mx); sum += v[i]; }
#pragma unroll
        for (int s = 16; s > 0; s >>= 1) sum += __shfl_xor_sync(0xffffffffu, sum, s);
        float inv = 1.f / sum;
#pragma unroll
        for (int i = 0; i < 16; i++) v[i] *= inv;
        float o0 = 0.f, o1 = 0.f, o2 = 0.f;
        for (int k = 0; k < 64; k++) {
            float p = 0.f;
#pragma unroll
            for (int i = 0; i < 16; i++) p = fmaf(v[i], base_sh[(lane + 32*i) * 65 + k], p);
#pragma unroll
            for (int s = 16; s > 0; s >>= 1) p += __shfl_xor_sync(0xffffffffu, p, s);
            o0 = fmaf(w4[0][k], p, o0); o1 = fmaf(w4[1][k], p, o1); o2 = fmaf(w4[2][k], p, o2);
        }
        if (lane == 0) { orow[m*3] = o0 + b4[0]; orow[m*3+1] = o1 + b4[1]; orow[m*3+2] = o2 + b4[2]; }
    }
}

// ------------------------------- launch ------------------------------------
extern "C" void kernel_launch(void* const* d_in, const int* in_sizes, int n_in,
                              void* d_out, int out_size)
{
    (void)in_sizes; (void)n_in; (void)out_size;
    const float* x     = (const float*)d_in[0];
    const float* xpart = (const float*)d_in[1];
    const float* mW1 = (const float*)d_in[2];
    const float* mg1 = (const float*)d_in[4];
    const float* mB1 = (const float*)d_in[5];
    const float* mW2 = (const float*)d_in[6];
    const float* mg2 = (const float*)d_in[8];
    const float* mB2 = (const float*)d_in[9];
    const float* mW3 = (const float*)d_in[10];
    const float* mg3 = (const float*)d_in[12];
    const float* mB3 = (const float*)d_in[13];
    const float* mW4 = (const float*)d_in[14];
    const float* mg4 = (const float*)d_in[16];
    const float* mB4 = (const float*)d_in[17];
    const float* aW1 = (const float*)d_in[18];
    const float* ag1 = (const float*)d_in[20];
    const float* aB1 = (const float*)d_in[21];
    const float* aW2 = (const float*)d_in[22];
    const float* ag2 = (const float*)d_in[24];
    const float* aB2 = (const float*)d_in[25];
    const float* aW3 = (const float*)d_in[26];
    const float* aW4 = (const float*)d_in[28];
    const float* ab4 = (const float*)d_in[29];
    float* out = (float*)d_out;

    float *bufA, *bufB, *h4, *t1, *t2, *t3, *psum, *psq, *sc, *sh;
    __nv_bfloat16 *Ahp, *Alp, *Xh, *Xl, *W1h, *W1l, *W2h, *W2l, *W3h, *W3l, *W4h, *W4l;
    cudaGetSymbolAddress((void**)&bufA, g_bufA);
    cudaGetSymbolAddress((void**)&bufB, g_bufB);
    cudaGetSymbolAddress((void**)&h4, g_h4);
    cudaGetSymbolAddress((void**)&t1, g_t1);
    cudaGetSymbolAddress((void**)&t2, g_t2);
    cudaGetSymbolAddress((void**)&t3, g_t3);
    cudaGetSymbolAddress((void**)&psum, g_psum);
    cudaGetSymbolAddress((void**)&psq, g_psq);
    cudaGetSymbolAddress((void**)&sc, g_scale);
    cudaGetSymbolAddress((void**)&sh, g_shift);
    cudaGetSymbolAddress((void**)&Ahp, g_Ah);
    cudaGetSymbolAddress((void**)&Alp, g_Al);
    cudaGetSymbolAddress((void**)&Xh, g_Xh);
    cudaGetSymbolAddress((void**)&Xl, g_Xl);
    cudaGetSymbolAddress((void**)&W1h, g_W1h);
    cudaGetSymbolAddress((void**)&W1l, g_W1l);
    cudaGetSymbolAddress((void**)&W2h, g_W2h);
    cudaGetSymbolAddress((void**)&W2l, g_W2l);
    cudaGetSymbolAddress((void**)&W3h, g_W3h);
    cudaGetSymbolAddress((void**)&W3l, g_W3l);
    cudaGetSymbolAddress((void**)&W4h, g_W4h);
    cudaGetSymbolAddress((void**)&W4l, g_W4l);

    static bool init_done = false;
    static cudaStream_t s2;
    static cudaEvent_t evFork, evJoin;
    if (!init_done) {
        cudaFuncSetAttribute(softmax_pts_kernel, cudaFuncAttributeMaxDynamicSharedMemorySize, 512 * 65 * 4);
        cudaFuncSetAttribute(gemm_mma2, cudaFuncAttributeMaxDynamicSharedMemorySize, 81920);
        cudaStreamCreateWithFlags(&s2, cudaStreamNonBlocking);
        cudaEventCreateWithFlags(&evFork, cudaEventDisableTiming);
        cudaEventCreateWithFlags(&evJoin, cudaEventDisableTiming);
        init_done = true;
    }

    const int SL = NBR * 512;
    const long MS512 = (long)MROWS * 512;
    const long MS64  = (long)MROWS * 64;
    const long MS128 = (long)MROWS * 128;

    cudaEventRecord(evFork, 0);
    cudaStreamWaitEvent(s2, evFork, 0);
    fps_kernel<<<32 * FPS_CL, 512, 0, s2>>>(xpart, out);
    cudaEventRecord(evJoin, s2);

    conv_plain_v<<<(NBR*512*256)/2048, 256>>>(mW1, W1h, W1l);
    conv_plain_v<<<(NBR*512*512)/2048, 256>>>(mW2, W2h, W2l);
    conv_plain_v<<<(NBR*512*512)/2048, 256>>>(mW3, W3h, W3l);
    conv_w4_v<<<(NBR*128*512)/2048, 256>>>(mW4, W4h, W4l);
    conv_plain_v<<<(MROWS*256)/2048, 256>>>(x, Xh, Xl);

    gemm_mma2<<<dim3(4, 128, NBR), 256, 81920>>>(Xh, Xl, W1h, W1l, bufA, psum, psq,
                                                 256, 0, 512L*256, 512);
    bn_finalize<<<16, 256>>>(psum, psq, mg1, mB1, sc, sh, NBR * 512);

    conv_bn_v<<<(NBR*MROWS*512)/2048, 256>>>(bufA, sc, sh, Ahp, Alp);
    gemm_mma2<<<dim3(4, 128, NBR), 256, 81920>>>(Ahp, Alp, W2h, W2l, bufB, psum, psq,
                                                 512, MS512, 512L*512, 512);
    bn_finalize<<<16, 256>>>(psum, psq, mg2, mB2, sc + SL, sh + SL, NBR * 512);

    conv_bn_v<<<(NBR*MROWS*512)/2048, 256>>>(bufB, sc + SL, sh + SL, Ahp, Alp);
    gemm_mma2<<<dim3(4, 128, NBR), 256, 81920>>>(Ahp, Alp, W3h, W3l, bufA, psum, psq,
                                                 512, MS512, 512L*512, 512);
    bn_finalize<<<16, 256>>>(psum, psq, mg3, mB3, sc + 2 * SL, sh + 2 * SL, NBR * 512);

    conv_bn_v<<<(NBR*MROWS*512)/2048, 256>>>(bufA, sc + 2 * SL, sh + 2 * SL, Ahp, Alp);
    gemm_mma2<<<dim3(1, 128, NBR), 256, 81920>>>(Ahp, Alp, W4h, W4l, h4, psum, psq,
                                                 512, MS512, 128L*512, 64);
    bn_finalize<<<2, 256>>>(psum, psq, mg4, mB4, sc + 3 * SL, sh + 3 * SL, NBR * 64);

    gemm_bn<64, 4, true, true><<<dim3(1, 128, NBR), 256>>>(
        h4, aW1, t1, sc + 3 * SL, sh + 3 * SL, psum, psq, MROWS, 64, 64, MS64);
    bn_finalize<<<2, 256>>>(psum, psq, ag1, aB1, sc + 4 * SL, sh + 4 * SL, NBR * 64);

    gemm_bn<128, 8, true, true><<<dim3(1, 128, NBR), 256>>>(
        t1, aW2, t2, sc + 4 * SL, sh + 4 * SL, psum, psq, MROWS, 128, 64, MS64);
    bn_finalize<<<4, 256>>>(psum, psq, ag2, aB2, sc + 5 * SL, sh + 5 * SL, NBR * 128);

    gemm_bn<128, 8, true, false><<<dim3(1, 128, NBR), 256>>>(
        t2, aW3, t3, sc + 5 * SL, sh + 5 * SL, nullptr, nullptr, MROWS, 128, 128, MS128);

    softmax_pts_kernel<<<dim3(32, NBR), 256, 512 * 65 * 4>>>(
        t3, h4, sc + 3 * SL, sh + 3 * SL, aW4, ab4, out);

    cudaStreamWaitEvent(0, evJoin, 0);
}

// round 10
// speedup vs baseline: 1.5562x; 1.5562x over previous
#include <cuda_runtime.h>
#include <cuda_bf16.h>
#include <cstdint>
#include <cstddef>

#define NBR 8
#define MROWS 16384
#define BN_EPS 1e-5f

__device__ __align__(256) float g_bufA[(size_t)NBR * MROWS * 512];
__device__ __align__(256) float g_bufB[(size_t)NBR * MROWS * 512];
__device__ __align__(256) float g_h4 [(size_t)NBR * MROWS * 64];
__device__ __align__(256) float g_t1 [(size_t)NBR * MROWS * 64];
__device__ __align__(256) float g_t2 [(size_t)NBR * MROWS * 128];
__device__ __align__(256) float g_t3 [(size_t)NBR * MROWS * 128];
__device__ float g_psum [NBR * 512 * 128];
__device__ float g_psq  [NBR * 512 * 128];
__device__ float g_scale[6 * NBR * 512];
__device__ float g_shift[6 * NBR * 512];
__device__ __align__(16) __nv_bfloat16 g_Ah[(size_t)NBR * MROWS * 512];
__device__ __align__(16) __nv_bfloat16 g_Al[(size_t)NBR * MROWS * 512];
__device__ __align__(16) __nv_bfloat16 g_Xh[(size_t)MROWS * 256];
__device__ __align__(16) __nv_bfloat16 g_Xl[(size_t)MROWS * 256];
__device__ __align__(16) __nv_bfloat16 g_W1h[NBR * 512 * 256];
__device__ __align__(16) __nv_bfloat16 g_W1l[NBR * 512 * 256];
__device__ __align__(16) __nv_bfloat16 g_W2h[NBR * 512 * 512];
__device__ __align__(16) __nv_bfloat16 g_W2l[NBR * 512 * 512];
__device__ __align__(16) __nv_bfloat16 g_W3h[NBR * 512 * 512];
__device__ __align__(16) __nv_bfloat16 g_W3l[NBR * 512 * 512];
__device__ __align__(16) __nv_bfloat16 g_W4h[NBR * 128 * 512];
__device__ __align__(16) __nv_bfloat16 g_W4l[NBR * 128 * 512];
// A-chain operands (bf16 split)
__device__ __align__(16) __nv_bfloat16 g_B1h[(size_t)NBR * MROWS * 64];
__device__ __align__(16) __nv_bfloat16 g_B1l[(size_t)NBR * MROWS * 64];
__device__ __align__(16) __nv_bfloat16 g_B2h[(size_t)NBR * MROWS * 64];
__device__ __align__(16) __nv_bfloat16 g_B2l[(size_t)NBR * MROWS * 64];
__device__ __align__(16) __nv_bfloat16 g_B3h[(size_t)NBR * MROWS * 128];
__device__ __align__(16) __nv_bfloat16 g_B3l[(size_t)NBR * MROWS * 128];
__device__ __align__(16) __nv_bfloat16 g_Wa1h[NBR * 128 * 64];
__device__ __align__(16) __nv_bfloat16 g_Wa1l[NBR * 128 * 64];
__device__ __align__(16) __nv_bfloat16 g_Wa2h[NBR * 128 * 64];
__device__ __align__(16) __nv_bfloat16 g_Wa2l[NBR * 128 * 64];
__device__ __align__(16) __nv_bfloat16 g_Wa3h[NBR * 128 * 128];
__device__ __align__(16) __nv_bfloat16 g_Wa3l[NBR * 128 * 128];

__device__ __forceinline__ uint32_t smem_u32(const void* p) {
    uint32_t a;
    asm("{ .reg .u64 t; cvta.to.shared.u64 t, %1; cvt.u32.u64 %0, t; }" : "=r"(a) : "l"(p));
    return a;
}
__device__ __forceinline__ void stc_f32(uint32_t sa, uint32_t rank, float v) {
    uint32_t r;
    asm volatile("mapa.shared::cluster.u32 %0, %1, %2;" : "=r"(r) : "r"(sa), "r"(rank));
    asm volatile("st.shared::cluster.f32 [%0], %1;" :: "r"(r), "f"(v) : "memory");
}
__device__ __forceinline__ void stc_u32(uint32_t sa, uint32_t rank, uint32_t v) {
    uint32_t r;
    asm volatile("mapa.shared::cluster.u32 %0, %1, %2;" : "=r"(r) : "r"(sa), "r"(rank));
    asm volatile("st.shared::cluster.u32 [%0], %1;" :: "r"(r), "r"(v) : "memory");
}
__device__ __forceinline__ void cpa16(uint32_t d, const void* g) {
    asm volatile("cp.async.cg.shared.global [%0], [%1], 16;" :: "r"(d), "l"(g));
}
#define CP_COMMIT() asm volatile("cp.async.commit_group;")
#define CP_WAIT(N)  asm volatile("cp.async.wait_group %0;" :: "n"(N))
#define LDSM4(R, ADDR) \
    asm volatile("ldmatrix.sync.aligned.m8n8.x4.shared.b16 {%0,%1,%2,%3}, [%4];" \
        : "=r"((R)[0]), "=r"((R)[1]), "=r"((R)[2]), "=r"((R)[3]) : "r"(ADDR))
#define MMA16816(D, A, B0, B1) \
    asm volatile("mma.sync.aligned.m16n8k16.row.col.f32.bf16.bf16.f32 " \
        "{%0,%1,%2,%3}, {%4,%5,%6,%7}, {%8,%9}, {%0,%1,%2,%3};" \
        : "+f"((D)[0]), "+f"((D)[1]), "+f"((D)[2]), "+f"((D)[3]) \
        : "r"((A)[0]), "r"((A)[1]), "r"((A)[2]), "r"((A)[3]), "r"(B0), "r"(B1))

// ------------------------------ FPS (proven) --------------------------------
#define FPS_CL 4
__global__ void __cluster_dims__(FPS_CL,1,1) __launch_bounds__(512,1)
fps_kernel(const float* __restrict__ xpart, float* __restrict__ out)
{
    uint32_t rank; asm("mov.u32 %0, %%cluster_ctarank;" : "=r"(rank));
    int b = blockIdx.x / FPS_CL;
    const float* xp = xpart + (size_t)b * 32768 * 3;
    int tid = threadIdx.x, lane = tid & 31, warp = tid >> 5;
    int pbase = (int)rank * 8192;
    float px[16], py[16], pz[16], dd[16];
#pragma unroll
    for (int i = 0; i < 16; i++) {
        int p = pbase + tid + 512 * i;
        px[i] = xp[p*3]; py[i] = xp[p*3+1]; pz[i] = xp[p*3+2]; dd[i] = 1e10f;
    }
    __shared__ float wv_[16]; __shared__ int wi_[16];
    __shared__ float wx_[16], wy_[16], wz_[16];
    __shared__ float cval[2][FPS_CL]; __shared__ int cidx[2][FPS_CL];
    __shared__ float cxx[2][FPS_CL], cyy[2][FPS_CL], czz[2][FPS_CL];
    float curx = xp[0], cury = xp[1], curz = xp[2];
    float* orow = out + ((size_t)b * 2048 + 1024) * 3;
    if (rank == 0 && tid == 0) { orow[0]=curx; orow[1]=cury; orow[2]=curz; }

    for (int t = 1; t < 1024; t++) {
        float bv = -1.f; int bi = 0x7fffffff;
        float bx = 0.f, by = 0.f, bz = 0.f;
#pragma unroll
        for (int i = 0; i < 16; i++) {
            float dx = __fsub_rn(px[i], curx), dy = __fsub_rn(py[i], cury), dz = __fsub_rn(pz[i], curz);
            float d = __fadd_rn(__fadd_rn(__fmul_rn(dx,dx), __fmul_rn(dy,dy)), __fmul_rn(dz,dz));
            dd[i] = fminf(dd[i], d);
            int gi = pbase + tid + 512 * i;
            if (dd[i] > bv || (dd[i] == bv && gi < bi)) { bv=dd[i]; bi=gi; bx=px[i]; by=py[i]; bz=pz[i]; }
        }
#pragma unroll
        for (int s = 16; s > 0; s >>= 1) {
            float ov = __shfl_down_sync(0xffffffffu, bv, s);
            int   oi = __shfl_down_sync(0xffffffffu, bi, s);
            float ox = __shfl_down_sync(0xffffffffu, bx, s);
            float oy = __shfl_down_sync(0xffffffffu, by, s);
            float oz = __shfl_down_sync(0xffffffffu, bz, s);
            if (ov > bv || (ov == bv && oi < bi)) { bv=ov; bi=oi; bx=ox; by=oy; bz=oz; }
        }
        if (lane == 0) { wv_[warp]=bv; wi_[warp]=bi; wx_[warp]=bx; wy_[warp]=by; wz_[warp]=bz; }
        __syncthreads();
        int par = t & 1;
        if (warp == 0) {
            bv = (lane < 16) ? wv_[lane] : -1.f;
            bi = (lane < 16) ? wi_[lane] : 0x7fffffff;
            bx = (lane < 16) ? wx_[lane] : 0.f;
            by = (lane < 16) ? wy_[lane] : 0.f;
            bz = (lane < 16) ? wz_[lane] : 0.f;
#pragma unroll
            for (int s = 8; s > 0; s >>= 1) {
                float ov = __shfl_down_sync(0xffffffffu, bv, s);
                int   oi = __shfl_down_sync(0xffffffffu, bi, s);
                float ox = __shfl_down_sync(0xffffffffu, bx, s);
                float oy = __shfl_down_sync(0xffffffffu, by, s);
                float oz = __shfl_down_sync(0xffffffffu, bz, s);
                if (ov > bv || (ov == bv && oi < bi)) { bv=ov; bi=oi; bx=ox; by=oy; bz=oz; }
            }
            if (lane == 0) {
                for (uint32_t r = 0; r < FPS_CL; r++) {
                    stc_f32(smem_u32(&cval[par][rank]), r, bv);
                    stc_u32(smem_u32(&cidx[par][rank]), r, (uint32_t)bi);
                    stc_f32(smem_u32(&cxx[par][rank]), r, bx);
                    stc_f32(smem_u32(&cyy[par][rank]), r, by);
                    stc_f32(smem_u32(&czz[par][rank]), r, bz);
                }
            }
        }
        asm volatile("barrier.cluster.arrive.aligned;" ::: "memory");
        asm volatile("barrier.cluster.wait.aligned;" ::: "memory");
        float vv = cval[par][0]; int vi = cidx[par][0];
        float nx = cxx[par][0], ny = cyy[par][0], nz = czz[par][0];
#pragma unroll
        for (int r = 1; r < FPS_CL; r++) {
            float ov = cval[par][r]; int oi = cidx[par][r];
            if (ov > vv || (ov == vv && oi < vi)) { vv=ov; vi=oi; nx=cxx[par][r]; ny=cyy[par][r]; nz=czz[par][r]; }
        }
        curx = nx; cury = ny; curz = nz;
        if (rank == 0 && tid == 0) { orow[t*3]=nx; orow[t*3+1]=ny; orow[t*3+2]=nz; }
    }
}

// ------------------------- conversion passes (scalar, proven) ---------------
__global__ void conv_plain(const float* __restrict__ S, __nv_bfloat16* __restrict__ H,
                           __nv_bfloat16* __restrict__ L, int nPairs)
{
    int p = blockIdx.x * 256 + threadIdx.x;
    if (p >= nPairs) return;
    float2 v = *(const float2*)(S + (size_t)p * 2);
    __nv_bfloat162 hp, lp;
    hp.x = __float2bfloat16(v.x); hp.y = __float2bfloat16(v.y);
    lp.x = __float2bfloat16(v.x - __bfloat162float(hp.x));
    lp.y = __float2bfloat16(v.y - __bfloat162float(hp.y));
    *(__nv_bfloat162*)(H + (size_t)p * 2) = hp;
    *(__nv_bfloat162*)(L + (size_t)p * 2) = lp;
}
// weight [NBR][64][K] -> padded [NBR][128][K] (rows 64..127 zero); lk = log2(K)
__global__ void conv_wpad_g(const float* __restrict__ S, __nv_bfloat16* __restrict__ H,
                            __nv_bfloat16* __restrict__ L, int K, int lk)
{
    int i2 = blockIdx.x * 256 + threadIdx.x;
    int idx = i2 * 2;
    int k = idx & (K - 1), n = (idx >> lk) & 127, z = idx >> (lk + 7);
    __nv_bfloat162 hp, lp;
    if (n < 64) {
        float2 v = *(const float2*)(S + ((size_t)z * 64 + n) * K + k);
        hp.x = __float2bfloat16(v.x); hp.y = __float2bfloat16(v.y);
        lp.x = __float2bfloat16(v.x - __bfloat162float(hp.x));
        lp.y = __float2bfloat16(v.y - __bfloat162float(hp.y));
    } else {
        hp.x = hp.y = lp.x = lp.y = __float2bfloat16(0.f);
    }
    *(__nv_bfloat162*)(H + (size_t)idx) = hp;
    *(__nv_bfloat162*)(L + (size_t)idx) = lp;
}
// BN+ReLU apply + split for C = 1<<lc channels; sc/sh pre-offset to layer slice
__global__ void conv_bn_g(const float* __restrict__ raw, const float* __restrict__ sc,
                          const float* __restrict__ sh, __nv_bfloat16* __restrict__ H,
                          __nv_bfloat16* __restrict__ L, int lc)
{
    int i2 = blockIdx.x * 256 + threadIdx.x;
    size_t idx = (size_t)i2 * 2;
    int C = 1 << lc;
    int k = (int)(idx & (C - 1));
    int row = (int)(idx >> lc);
    int z = row >> 14;
    float2 v = *(const float2*)(raw + idx);
    float a0 = fmaxf(fmaf(v.x, sc[z*C+k],   sh[z*C+k]),   0.f);
    float a1 = fmaxf(fmaf(v.y, sc[z*C+k+1], sh[z*C+k+1]), 0.f);
    __nv_bfloat162 hp, lp;
    hp.x = __float2bfloat16(a0); hp.y = __float2bfloat16(a1);
    lp.x = __float2bfloat16(a0 - __bfloat162float(hp.x));
    lp.y = __float2bfloat16(a1 - __bfloat162float(hp.y));
    *(__nv_bfloat162*)(H + idx) = hp;
    *(__nv_bfloat162*)(L + idx) = lp;
}

// -------------- bf16-split tensor-core GEMM, cp.async, 2 CTAs/SM ----------
__global__ void __launch_bounds__(256, 2)
gemm_mma2(const __nv_bfloat16* __restrict__ Agh, const __nv_bfloat16* __restrict__ Agl,
          const __nv_bfloat16* __restrict__ Bgh, const __nv_bfloat16* __restrict__ Bgl,
          float* __restrict__ Call, float* __restrict__ psum, float* __restrict__ psq,
          int K, long aStride, long bStride, int Nout)
{
    extern __shared__ __align__(16) uint32_t sm[];
    int bx = blockIdx.x, by = blockIdx.y, z = blockIdx.z;
    int tid = threadIdx.x, lane = tid & 31, w = tid >> 5;
    int wm = w & 1, wn = w >> 1;
    int m0 = by * 128, n0 = bx * 128, KC = K >> 5;
    const __nv_bfloat16* Ah = Agh + (size_t)z * aStride;
    const __nv_bfloat16* Al = Agl + (size_t)z * aStride;
    const __nv_bfloat16* Bh = Bgh + (size_t)z * bStride;
    const __nv_bfloat16* Bl = Bgl + (size_t)z * bStride;
    uint32_t sbase = smem_u32(sm);

    int lr = tid >> 1, half = tid & 1;
    const __nv_bfloat16* Ar_h = Ah + (size_t)(m0 + lr) * K + half * 16;
    const __nv_bfloat16* Ar_l = Al + (size_t)(m0 + lr) * K + half * 16;
    const __nv_bfloat16* Br_h = Bh + (size_t)(n0 + lr) * K + half * 16;
    const __nv_bfloat16* Br_l = Bl + (size_t)(n0 + lr) * K + half * 16;
    uint32_t drow = lr * 80 + half * 32;

    auto fill = [&](int kc, int s) {
        uint32_t st = sbase + s * 40960;
        int go = kc * 32;
        cpa16(st + drow,                Ar_h + go);
        cpa16(st + drow + 16,           Ar_h + go + 8);
        cpa16(st + 10240 + drow,        Ar_l + go);
        cpa16(st + 10240 + drow + 16,   Ar_l + go + 8);
        cpa16(st + 20480 + drow,        Br_h + go);
        cpa16(st + 20480 + drow + 16,   Br_h + go + 8);
        cpa16(st + 30720 + drow,        Br_l + go);
        cpa16(st + 30720 + drow + 16,   Br_l + go + 8);
    };

    float acc[4][4][4];
#pragma unroll
    for (int i = 0; i < 4; i++)
#pragma unroll
        for (int j = 0; j < 4; j++)
#pragma unroll
            for (int e = 0; e < 4; e++) acc[i][j][e] = 0.f;

    fill(0, 0); CP_COMMIT();
    if (KC > 1) { fill(1, 1); CP_COMMIT(); }

    int arow = lane & 15, kh = (lane >> 4) * 8;
    int bn_ = ((lane >> 4) & 1) * 8 + (lane & 7), bk = ((lane >> 3) & 1) * 8;

    for (int kc = 0; kc < KC; kc++) {
        int s = kc & 1;
        if (kc + 1 < KC) { CP_WAIT(1); } else { CP_WAIT(0); }
        __syncthreads();
        uint32_t abase = sbase + s * 40960 + (wm * 64) * 80;
        uint32_t bbase = sbase + s * 40960 + 20480 + (wn * 32) * 80;
#pragma unroll
        for (int ks = 0; ks < 2; ks++) {
            uint32_t bh[2][4], blr[2][4];
#pragma unroll
            for (int g = 0; g < 2; g++) {
                uint32_t bd = bbase + (g*16 + bn_) * 80 + (ks*16 + bk) * 2;
                LDSM4(bh[g], bd);
                LDSM4(blr[g], bd + 10240);
            }
#pragma unroll
            for (int mt = 0; mt < 4; mt++) {
                uint32_t ah[4], alr[4];
                uint32_t ad = abase + (mt*16 + arow) * 80 + (ks*16 + kh) * 2;
                LDSM4(ah, ad);
                LDSM4(alr, ad + 10240);
#pragma unroll
                for (int nt = 0; nt < 4; nt++) {
                    int g = nt >> 1, p = (nt & 1) * 2;
                    MMA16816(acc[mt][nt], ah,  bh[g][p],  bh[g][p+1]);
                    MMA16816(acc[mt][nt], ah,  blr[g][p], blr[g][p+1]);
                    MMA16816(acc[mt][nt], alr, bh[g][p],  bh[g][p+1]);
                }
            }
        }
        __syncthreads();
        if (kc + 2 < KC) { fill(kc + 2, s); CP_COMMIT(); }
    }

    float* cs = (float*)sm;
#pragma unroll
    for (int mt = 0; mt < 4; mt++)
#pragma unroll
        for (int nt = 0; nt < 4; nt++) {
            int r = wm*64 + mt*16 + (lane >> 2);
            int c = wn*32 + nt*8 + (lane & 3) * 2;
            *(float2*)(cs + r*132 + c)     = make_float2(acc[mt][nt][0], acc[mt][nt][1]);
            *(float2*)(cs + (r+8)*132 + c) = make_float2(acc[mt][nt][2], acc[mt][nt][3]);
        }
    __syncthreads();
    if (tid < 128 && n0 + tid < Nout) {
        float s = 0.f, q = 0.f;
#pragma unroll 8
        for (int r = 0; r < 128; r++) { float v = cs[r*132 + tid]; s += v; q = fmaf(v, v, q); }
        size_t ch = (size_t)z * Nout + n0 + tid;
        psum[ch * 128 + by] = s; psq[ch * 128 + by] = q;
    }
    float* C = Call + (size_t)z * MROWS * Nout;
#pragma unroll
    for (int i = 0; i < 16; i++) {
        int lin = tid + 256 * i;
        int r = lin >> 5, c4 = (lin & 31) * 4;
        if (n0 + c4 < Nout) {
            float4 v = *(float4*)(cs + r*132 + c4);
            *(float4*)(C + (size_t)(m0 + r) * Nout + n0 + c4) = v;
        }
    }
}

__global__ void bn_finalize(const float* __restrict__ psum, const float* __restrict__ psq,
                            const float* __restrict__ gam, const float* __restrict__ bet,
                            float* __restrict__ sc, float* __restrict__ sh, int total)
{
    int i = blockIdx.x * blockDim.x + threadIdx.x;
    if (i >= total) return;
    float s = 0.f, q = 0.f;
    const float* ps = psum + (size_t)i * 128;
    const float* pq = psq + (size_t)i * 128;
#pragma unroll 8
    for (int k = 0; k < 128; k++) { s += ps[k]; q += pq[k]; }
    float mean = s * (1.f / 16384.f);
    float var = fmaf(-mean, mean, q * (1.f / 16384.f));
    float g = gam[i] * rsqrtf(var + BN_EPS);
    sc[i] = g; sh[i] = fmaf(-mean, g, bet[i]);
}

// ----------------------------- softmax/pool (proven) ------------------------
__global__ void __launch_bounds__(256, 1)
softmax_pts_kernel(const float* __restrict__ t3, const float* __restrict__ h4raw,
                   const float* __restrict__ scaleL, const float* __restrict__ shiftL,
                   const float* __restrict__ aW4, const float* __restrict__ ab4,
                   float* __restrict__ out)
{
    int b = blockIdx.x, n = blockIdx.y;
    extern __shared__ float base_sh[];
    __shared__ float w4[3][64], b4[3];
    int tid = threadIdx.x;
    if (tid < 192) w4[tid / 64][tid % 64] = aW4[n * 192 + tid];
    if (tid < 3) b4[tid] = ab4[n * 3 + tid];
    const float* sc = scaleL + n * 64;
    const float* sh = shiftL + n * 64;
    const float* h4b = h4raw + ((size_t)n * MROWS + b * 512) * 64;
    for (int i = tid; i < 512 * 64; i += 256) {
        int l = i >> 6, k = i & 63;
        base_sh[l * 65 + k] = fmaxf(fmaf(h4b[i], sc[k], sh[k]), 0.f);
    }
    __syncthreads();
    int lane = tid & 31, warp = tid >> 5;
    const float* t3b = t3 + ((size_t)n * MROWS + b * 512) * 128;
    float* orow = out + ((size_t)b * 2048 + n * 128) * 3;
    for (int c = 0; c < 16; c++) {
        int m = warp + c * 8;
        float v[16], mx = -1e30f;
#pragma unroll
        for (int i = 0; i < 16; i++) { v[i] = t3b[(size_t)(lane + 32*i) * 128 + m]; mx = fmaxf(mx, v[i]); }
#pragma unroll
        for (int s = 16; s > 0; s >>= 1) mx = fmaxf(mx, __shfl_xor_sync(0xffffffffu, mx, s));
        float sum = 0.f;
#pragma unroll
        for (int i = 0; i < 16; i++) { v[i] = expf(v[i] - mx); sum += v[i]; }
#pragma unroll
        for (int s = 16; s > 0; s >>= 1) sum += __shfl_xor_sync(0xffffffffu, sum, s);
        float inv = 1.f / sum;
#pragma unroll
        for (int i = 0; i < 16; i++) v[i] *= inv;
        float o0 = 0.f, o1 = 0.f, o2 = 0.f;
        for (int k = 0; k < 64; k++) {
            float p = 0.f;
#pragma unroll
            for (int i = 0; i < 16; i++) p = fmaf(v[i], base_sh[(lane + 32*i) * 65 + k], p);
#pragma unroll
            for (int s = 16; s > 0; s >>= 1) p += __shfl_xor_sync(0xffffffffu, p, s);
            o0 = fmaf(w4[0][k], p, o0); o1 = fmaf(w4[1][k], p, o1); o2 = fmaf(w4[2][k], p, o2);
        }
        if (lane == 0) { orow[m*3] = o0 + b4[0]; orow[m*3+1] = o1 + b4[1]; orow[m*3+2] = o2 + b4[2]; }
    }
}

// ------------------------------- launch ------------------------------------
extern "C" void kernel_launch(void* const* d_in, const int* in_sizes, int n_in,
                              void* d_out, int out_size)
{
    (void)in_sizes; (void)n_in; (void)out_size;
    const float* x     = (const float*)d_in[0];
    const float* xpart = (const float*)d_in[1];
    const float* mW1 = (const float*)d_in[2];
    const float* mg1 = (const float*)d_in[4];
    const float* mB1 = (const float*)d_in[5];
    const float* mW2 = (const float*)d_in[6];
    const float* mg2 = (const float*)d_in[8];
    const float* mB2 = (const float*)d_in[9];
    const float* mW3 = (const float*)d_in[10];
    const float* mg3 = (const float*)d_in[12];
    const float* mB3 = (const float*)d_in[13];
    const float* mW4 = (const float*)d_in[14];
    const float* mg4 = (const float*)d_in[16];
    const float* mB4 = (const float*)d_in[17];
    const float* aW1 = (const float*)d_in[18];
    const float* ag1 = (const float*)d_in[20];
    const float* aB1 = (const float*)d_in[21];
    const float* aW2 = (const float*)d_in[22];
    const float* ag2 = (const float*)d_in[24];
    const float* aB2 = (const float*)d_in[25];
    const float* aW3 = (const float*)d_in[26];
    const float* aW4 = (const float*)d_in[28];
    const float* ab4 = (const float*)d_in[29];
    float* out = (float*)d_out;

    float *bufA, *bufB, *h4, *t1, *t2, *t3, *psum, *psq, *sc, *sh;
    __nv_bfloat16 *Ahp, *Alp, *Xh, *Xl, *W1h, *W1l, *W2h, *W2l, *W3h, *W3l, *W4h, *W4l;
    __nv_bfloat16 *B1h, *B1l, *B2h, *B2l, *B3h, *B3l;
    __nv_bfloat16 *Wa1h, *Wa1l, *Wa2h, *Wa2l, *Wa3h, *Wa3l;
    cudaGetSymbolAddress((void**)&bufA, g_bufA);
    cudaGetSymbolAddress((void**)&bufB, g_bufB);
    cudaGetSymbolAddress((void**)&h4, g_h4);
    cudaGetSymbolAddress((void**)&t1, g_t1);
    cudaGetSymbolAddress((void**)&t2, g_t2);
    cudaGetSymbolAddress((void**)&t3, g_t3);
    cudaGetSymbolAddress((void**)&psum, g_psum);
    cudaGetSymbolAddress((void**)&psq, g_psq);
    cudaGetSymbolAddress((void**)&sc, g_scale);
    cudaGetSymbolAddress((void**)&sh, g_shift);
    cudaGetSymbolAddress((void**)&Ahp, g_Ah);
    cudaGetSymbolAddress((void**)&Alp, g_Al);
    cudaGetSymbolAddress((void**)&Xh, g_Xh);
    cudaGetSymbolAddress((void**)&Xl, g_Xl);
    cudaGetSymbolAddress((void**)&W1h, g_W1h);
    cudaGetSymbolAddress((void**)&W1l, g_W1l);
    cudaGetSymbolAddress((void**)&W2h, g_W2h);
    cudaGetSymbolAddress((void**)&W2l, g_W2l);
    cudaGetSymbolAddress((void**)&W3h, g_W3h);
    cudaGetSymbolAddress((void**)&W3l, g_W3l);
    cudaGetSymbolAddress((void**)&W4h, g_W4h);
    cudaGetSymbolAddress((void**)&W4l, g_W4l);
    cudaGetSymbolAddress((void**)&B1h, g_B1h);
    cudaGetSymbolAddress((void**)&B1l, g_B1l);
    cudaGetSymbolAddress((void**)&B2h, g_B2h);
    cudaGetSymbolAddress((void**)&B2l, g_B2l);
    cudaGetSymbolAddress((void**)&B3h, g_B3h);
    cudaGetSymbolAddress((void**)&B3l, g_B3l);
    cudaGetSymbolAddress((void**)&Wa1h, g_Wa1h);
    cudaGetSymbolAddress((void**)&Wa1l, g_Wa1l);
    cudaGetSymbolAddress((void**)&Wa2h, g_Wa2h);
    cudaGetSymbolAddress((void**)&Wa2l, g_Wa2l);
    cudaGetSymbolAddress((void**)&Wa3h, g_Wa3h);
    cudaGetSymbolAddress((void**)&Wa3l, g_Wa3l);

    static bool init_done = false;
    static cudaStream_t s2;
    static cudaEvent_t evFork, evJoin;
    if (!init_done) {
        cudaFuncSetAttribute(softmax_pts_kernel, cudaFuncAttributeMaxDynamicSharedMemorySize, 512 * 65 * 4);
        cudaFuncSetAttribute(gemm_mma2, cudaFuncAttributeMaxDynamicSharedMemorySize, 81920);
        cudaStreamCreateWithFlags(&s2, cudaStreamNonBlocking);
        cudaEventCreateWithFlags(&evFork, cudaEventDisableTiming);
        cudaEventCreateWithFlags(&evJoin, cudaEventDisableTiming);
        init_done = true;
    }

    const int SL = NBR * 512;
    const long MS512 = (long)MROWS * 512;
    const long MS64  = (long)MROWS * 64;
    const long MS128 = (long)MROWS * 128;

    cudaEventRecord(evFork, 0);
    cudaStreamWaitEvent(s2, evFork, 0);
    fps_kernel<<<32 * FPS_CL, 512, 0, s2>>>(xpart, out);
    cudaEventRecord(evJoin, s2);

    // weight + x conversions
    conv_plain<<<(NBR*512*128)/256, 256>>>(mW1, W1h, W1l, NBR*512*128);
    conv_plain<<<(NBR*512*256)/256, 256>>>(mW2, W2h, W2l, NBR*512*256);
    conv_plain<<<(NBR*512*256)/256, 256>>>(mW3, W3h, W3l, NBR*512*256);
    conv_wpad_g<<<(NBR*128*512)/512, 256>>>(mW4, W4h, W4l, 512, 9);
    conv_wpad_g<<<(NBR*128*64)/512, 256>>>(aW1, Wa1h, Wa1l, 64, 6);
    conv_plain<<<(NBR*128*32)/256, 256>>>(aW2, Wa2h, Wa2l, NBR*128*32);
    conv_plain<<<(NBR*128*64)/256, 256>>>(aW3, Wa3h, Wa3l, NBR*128*64);
    conv_plain<<<(MROWS*128)/256, 256>>>(x, Xh, Xl, MROWS*128);

    // L1..L3 (tensor cores)
    gemm_mma2<<<dim3(4, 128, NBR), 256, 81920>>>(Xh, Xl, W1h, W1l, bufA, psum, psq,
                                                 256, 0, 512L*256, 512);
    bn_finalize<<<16, 256>>>(psum, psq, mg1, mB1, sc, sh, NBR * 512);

    conv_bn_g<<<(NBR*MROWS*512)/512, 256>>>(bufA, sc, sh, Ahp, Alp, 9);
    gemm_mma2<<<dim3(4, 128, NBR), 256, 81920>>>(Ahp, Alp, W2h, W2l, bufB, psum, psq,
                                                 512, MS512, 512L*512, 512);
    bn_finalize<<<16, 256>>>(psum, psq, mg2, mB2, sc + SL, sh + SL, NBR * 512);

    conv_bn_g<<<(NBR*MROWS*512)/512, 256>>>(bufB, sc + SL, sh + SL, Ahp, Alp, 9);
    gemm_mma2<<<dim3(4, 128, NBR), 256, 81920>>>(Ahp, Alp, W3h, W3l, bufA, psum, psq,
                                                 512, MS512, 512L*512, 512);
    bn_finalize<<<16, 256>>>(psum, psq, mg3, mB3, sc + 2 * SL, sh + 2 * SL, NBR * 512);

    // L4 (tensor cores, padded N)
    conv_bn_g<<<(NBR*MROWS*512)/512, 256>>>(bufA, sc + 2 * SL, sh + 2 * SL, Ahp, Alp, 9);
    gemm_mma2<<<dim3(1, 128, NBR), 256, 81920>>>(Ahp, Alp, W4h, W4l, h4, psum, psq,
                                                 512, MS512, 128L*512, 64);
    bn_finalize<<<2, 256>>>(psum, psq, mg4, mB4, sc + 3 * SL, sh + 3 * SL, NBR * 64);

    // A1 (tensor cores): base = BN(h4) -> t1
    conv_bn_g<<<(NBR*MROWS*64)/512, 256>>>(h4, sc + 3 * SL, sh + 3 * SL, B1h, B1l, 6);
    gemm_mma2<<<dim3(1, 128, NBR), 256, 81920>>>(B1h, B1l, Wa1h, Wa1l, t1, psum, psq,
                                                 64, MS64, 128L*64, 64);
    bn_finalize<<<2, 256>>>(psum, psq, ag1, aB1, sc + 4 * SL, sh + 4 * SL, NBR * 64);

    // A2 (tensor cores): BN(t1) -> t2
    conv_bn_g<<<(NBR*MROWS*64)/512, 256>>>(t1, sc + 4 * SL, sh + 4 * SL, B2h, B2l, 6);
    gemm_mma2<<<dim3(1, 128, NBR), 256, 81920>>>(B2h, B2l, Wa2h, Wa2l, t2, psum, psq,
                                                 64, MS64, 128L*64, 128);
    bn_finalize<<<4, 256>>>(psum, psq, ag2, aB2, sc + 5 * SL, sh + 5 * SL, NBR * 128);

    // A3 (tensor cores): BN(t2) -> t3 logits
    conv_bn_g<<<(NBR*MROWS*128)/512, 256>>>(t2, sc + 5 * SL, sh + 5 * SL, B3h, B3l, 7);
    gemm_mma2<<<dim3(1, 128, NBR), 256, 81920>>>(B3h, B3l, Wa3h, Wa3l, t3, psum, psq,
                                                 128, MS128, 128L*128, 128);

    softmax_pts_kernel<<<dim3(32, NBR), 256, 512 * 65 * 4>>>(
        t3, h4, sc + 3 * SL, sh + 3 * SL, aW4, ab4, out);

    cudaStreamWaitEvent(0, evJoin, 0);
}

// round 12
// speedup vs baseline: 1.8947x; 1.2175x over previous
#include <cuda_runtime.h>
#include <cuda_fp16.h>
#include <cstdint>
#include <cstddef>

#define NBR 8
#define MROWS 16384
#define BN_EPS 1e-5f

__device__ __align__(256) float g_bufA[(size_t)NBR * MROWS * 512];
__device__ __align__(256) float g_bufB[(size_t)NBR * MROWS * 512];
__device__ __align__(256) float g_h4 [(size_t)NBR * MROWS * 64];
__device__ __align__(256) float g_t1 [(size_t)NBR * MROWS * 64];
__device__ __align__(256) float g_t2 [(size_t)NBR * MROWS * 128];
__device__ __align__(256) float g_t3 [(size_t)NBR * MROWS * 128];
__device__ float g_psum [NBR * 512 * 128];
__device__ float g_psq  [NBR * 512 * 128];
__device__ float g_scale[6 * NBR * 512];
__device__ float g_shift[6 * NBR * 512];
// fp16 operand panels
__device__ __align__(16) __half g_Af [(size_t)NBR * MROWS * 512];
__device__ __align__(16) __half g_Xf [(size_t)MROWS * 256];
__device__ __align__(16) __half g_W1f[NBR * 512 * 256];
__device__ __align__(16) __half g_W2f[NBR * 512 * 512];
__device__ __align__(16) __half g_W3f[NBR * 512 * 512];
__device__ __align__(16) __half g_W4f[NBR * 128 * 512];
__device__ __align__(16) __half g_B1f[(size_t)NBR * MROWS * 64];
__device__ __align__(16) __half g_B2f[(size_t)NBR * MROWS * 64];
__device__ __align__(16) __half g_B3f[(size_t)NBR * MROWS * 128];
__device__ __align__(16) __half g_Wa1f[NBR * 128 * 64];
__device__ __align__(16) __half g_Wa2f[NBR * 128 * 64];
__device__ __align__(16) __half g_Wa3f[NBR * 128 * 128];

__device__ __forceinline__ uint32_t smem_u32(const void* p) {
    uint32_t a;
    asm("{ .reg .u64 t; cvta.to.shared.u64 t, %1; cvt.u32.u64 %0, t; }" : "=r"(a) : "l"(p));
    return a;
}
__device__ __forceinline__ void stc_f32(uint32_t sa, uint32_t rank, float v) {
    uint32_t r;
    asm volatile("mapa.shared::cluster.u32 %0, %1, %2;" : "=r"(r) : "r"(sa), "r"(rank));
    asm volatile("st.shared::cluster.f32 [%0], %1;" :: "r"(r), "f"(v) : "memory");
}
__device__ __forceinline__ void stc_u32(uint32_t sa, uint32_t rank, uint32_t v) {
    uint32_t r;
    asm volatile("mapa.shared::cluster.u32 %0, %1, %2;" : "=r"(r) : "r"(sa), "r"(rank));
    asm volatile("st.shared::cluster.u32 [%0], %1;" :: "r"(r), "r"(v) : "memory");
}
__device__ __forceinline__ void cpa16(uint32_t d, const void* g) {
    asm volatile("cp.async.cg.shared.global [%0], [%1], 16;" :: "r"(d), "l"(g));
}
#define CP_COMMIT() asm volatile("cp.async.commit_group;")
#define CP_WAIT(N)  asm volatile("cp.async.wait_group %0;" :: "n"(N))
#define LDSM4(R, ADDR) \
    asm volatile("ldmatrix.sync.aligned.m8n8.x4.shared.b16 {%0,%1,%2,%3}, [%4];" \
        : "=r"((R)[0]), "=r"((R)[1]), "=r"((R)[2]), "=r"((R)[3]) : "r"(ADDR))
#define MMAF16(D, A, B0, B1) \
    asm volatile("mma.sync.aligned.m16n8k16.row.col.f32.f16.f16.f32 " \
        "{%0,%1,%2,%3}, {%4,%5,%6,%7}, {%8,%9}, {%0,%1,%2,%3};" \
        : "+f"((D)[0]), "+f"((D)[1]), "+f"((D)[2]), "+f"((D)[3]) \
        : "r"((A)[0]), "r"((A)[1]), "r"((A)[2]), "r"((A)[3]), "r"(B0), "r"(B1))

// ------------------------------ FPS (proven) --------------------------------
#define FPS_CL 4
__global__ void __cluster_dims__(FPS_CL,1,1) __launch_bounds__(512,1)
fps_kernel(const float* __restrict__ xpart, float* __restrict__ out)
{
    uint32_t rank; asm("mov.u32 %0, %%cluster_ctarank;" : "=r"(rank));
    int b = blockIdx.x / FPS_CL;
    const float* xp = xpart + (size_t)b * 32768 * 3;
    int tid = threadIdx.x, lane = tid & 31, warp = tid >> 5;
    int pbase = (int)rank * 8192;
    float px[16], py[16], pz[16], dd[16];
#pragma unroll
    for (int i = 0; i < 16; i++) {
        int p = pbase + tid + 512 * i;
        px[i] = xp[p*3]; py[i] = xp[p*3+1]; pz[i] = xp[p*3+2]; dd[i] = 1e10f;
    }
    __shared__ float wv_[16]; __shared__ int wi_[16];
    __shared__ float wx_[16], wy_[16], wz_[16];
    __shared__ float cval[2][FPS_CL]; __shared__ int cidx[2][FPS_CL];
    __shared__ float cxx[2][FPS_CL], cyy[2][FPS_CL], czz[2][FPS_CL];
    float curx = xp[0], cury = xp[1], curz = xp[2];
    float* orow = out + ((size_t)b * 2048 + 1024) * 3;
    if (rank == 0 && tid == 0) { orow[0]=curx; orow[1]=cury; orow[2]=curz; }

    for (int t = 1; t < 1024; t++) {
        float bv = -1.f; int bi = 0x7fffffff;
        float bx = 0.f, by = 0.f, bz = 0.f;
#pragma unroll
        for (int i = 0; i < 16; i++) {
            float dx = __fsub_rn(px[i], curx), dy = __fsub_rn(py[i], cury), dz = __fsub_rn(pz[i], curz);
            float d = __fadd_rn(__fadd_rn(__fmul_rn(dx,dx), __fmul_rn(dy,dy)), __fmul_rn(dz,dz));
            dd[i] = fminf(dd[i], d);
            int gi = pbase + tid + 512 * i;
            if (dd[i] > bv || (dd[i] == bv && gi < bi)) { bv=dd[i]; bi=gi; bx=px[i]; by=py[i]; bz=pz[i]; }
        }
#pragma unroll
        for (int s = 16; s > 0; s >>= 1) {
            float ov = __shfl_down_sync(0xffffffffu, bv, s);
            int   oi = __shfl_down_sync(0xffffffffu, bi, s);
            float ox = __shfl_down_sync(0xffffffffu, bx, s);
            float oy = __shfl_down_sync(0xffffffffu, by, s);
            float oz = __shfl_down_sync(0xffffffffu, bz, s);
            if (ov > bv || (ov == bv && oi < bi)) { bv=ov; bi=oi; bx=ox; by=oy; bz=oz; }
        }
        if (lane == 0) { wv_[warp]=bv; wi_[warp]=bi; wx_[warp]=bx; wy_[warp]=by; wz_[warp]=bz; }
        __syncthreads();
        int par = t & 1;
        if (warp == 0) {
            bv = (lane < 16) ? wv_[lane] : -1.f;
            bi = (lane < 16) ? wi_[lane] : 0x7fffffff;
            bx = (lane < 16) ? wx_[lane] : 0.f;
            by = (lane < 16) ? wy_[lane] : 0.f;
            bz = (lane < 16) ? wz_[lane] : 0.f;
#pragma unroll
            for (int s = 8; s > 0; s >>= 1) {
                float ov = __shfl_down_sync(0xffffffffu, bv, s);
                int   oi = __shfl_down_sync(0xffffffffu, bi, s);
                float ox = __shfl_down_sync(0xffffffffu, bx, s);
                float oy = __shfl_down_sync(0xffffffffu, by, s);
                float oz = __shfl_down_sync(0xffffffffu, bz, s);
                if (ov > bv || (ov == bv && oi < bi)) { bv=ov; bi=oi; bx=ox; by=oy; bz=oz; }
            }
            if (lane == 0) {
                for (uint32_t r = 0; r < FPS_CL; r++) {
                    stc_f32(smem_u32(&cval[par][rank]), r, bv);
                    stc_u32(smem_u32(&cidx[par][rank]), r, (uint32_t)bi);
                    stc_f32(smem_u32(&cxx[par][rank]), r, bx);
                    stc_f32(smem_u32(&cyy[par][rank]), r, by);
                    stc_f32(smem_u32(&czz[par][rank]), r, bz);
                }
            }
        }
        asm volatile("barrier.cluster.arrive.aligned;" ::: "memory");
        asm volatile("barrier.cluster.wait.aligned;" ::: "memory");
        float vv = cval[par][0]; int vi = cidx[par][0];
        float nx = cxx[par][0], ny = cyy[par][0], nz = czz[par][0];
#pragma unroll
        for (int r = 1; r < FPS_CL; r++) {
            float ov = cval[par][r]; int oi = cidx[par][r];
            if (ov > vv || (ov == vv && oi < vi)) { vv=ov; vi=oi; nx=cxx[par][r]; ny=cyy[par][r]; nz=czz[par][r]; }
        }
        curx = nx; cury = ny; curz = nz;
        if (rank == 0 && tid == 0) { orow[t*3]=nx; orow[t*3+1]=ny; orow[t*3+2]=nz; }
    }
}

// ------------------------- fp16 conversion passes ---------------------------
__global__ void conv_plain(const float* __restrict__ S, __half* __restrict__ H, int nPairs)
{
    int p = blockIdx.x * 256 + threadIdx.x;
    if (p >= nPairs) return;
    float2 v = *(const float2*)(S + (size_t)p * 2);
    __half2 h; h.x = __float2half_rn(v.x); h.y = __float2half_rn(v.y);
    *(__half2*)(H + (size_t)p * 2) = h;
}
// weight [NBR][64][K] -> padded [NBR][128][K] (rows 64..127 zero); lk = log2(K)
__global__ void conv_wpad_g(const float* __restrict__ S, __half* __restrict__ H, int K, int lk)
{
    int i2 = blockIdx.x * 256 + threadIdx.x;
    int idx = i2 * 2;
    int k = idx & (K - 1), n = (idx >> lk) & 127, z = idx >> (lk + 7);
    __half2 h;
    if (n < 64) {
        float2 v = *(const float2*)(S + ((size_t)z * 64 + n) * K + k);
        h.x = __float2half_rn(v.x); h.y = __float2half_rn(v.y);
    } else {
        h.x = h.y = __float2half_rn(0.f);
    }
    *(__half2*)(H + (size_t)idx) = h;
}
// BN+ReLU apply -> fp16; C = 1<<lc channels; sc/sh pre-offset to layer slice
__global__ void conv_bn_g(const float* __restrict__ raw, const float* __restrict__ sc,
                          const float* __restrict__ sh, __half* __restrict__ H, int lc)
{
    int i2 = blockIdx.x * 256 + threadIdx.x;
    size_t idx = (size_t)i2 * 2;
    int C = 1 << lc;
    int k = (int)(idx & (C - 1));
    int row = (int)(idx >> lc);
    int z = row >> 14;
    float2 v = *(const float2*)(raw + idx);
    float a0 = fmaxf(fmaf(v.x, sc[z*C+k],   sh[z*C+k]),   0.f);
    float a1 = fmaxf(fmaf(v.y, sc[z*C+k+1], sh[z*C+k+1]), 0.f);
    __half2 h; h.x = __float2half_rn(a0); h.y = __float2half_rn(a1);
    *(__half2*)(H + idx) = h;
}

// -------------- fp16 tensor-core GEMM, 4-stage cp.async, 2 CTAs/SM ---------
// stage layout: A 128 rows x 32 half (pitch 80B) = 10240B, B same at +10240
#define STG 20480
__global__ void __launch_bounds__(256, 2)
gemm_f16(const __half* __restrict__ Ag, const __half* __restrict__ Bg,
         float* __restrict__ Call, float* __restrict__ psum, float* __restrict__ psq,
         int K, long aStride, long bStride, int Nout)
{
    extern __shared__ __align__(16) uint32_t sm[];
    int bx = blockIdx.x, by = blockIdx.y, z = blockIdx.z;
    int tid = threadIdx.x, lane = tid & 31, w = tid >> 5;
    int wm = w & 1, wn = w >> 1;
    int m0 = by * 128, n0 = bx * 128, KC = K >> 5;
    const __half* A = Ag + (size_t)z * aStride;
    const __half* B = Bg + (size_t)z * bStride;
    uint32_t sbase = smem_u32(sm);

    // loader: thread t -> row (t&127) of panel (t>>7); 64B per row = 4 x 16B
    int lrow = tid & 127, pan = tid >> 7;
    const __half* Grow = (pan ? B + (size_t)(n0 + lrow) * K
                              : A + (size_t)(m0 + lrow) * K);
    uint32_t drow = (uint32_t)pan * 10240 + lrow * 80;

    auto fill = [&](int kc, int s) {
        uint32_t st = sbase + s * STG + drow;
        const __half* g = Grow + kc * 32;
        cpa16(st,      g);
        cpa16(st + 16, g + 8);
        cpa16(st + 32, g + 16);
        cpa16(st + 48, g + 24);
    };

    float acc[4][4][4];
#pragma unroll
    for (int i = 0; i < 4; i++)
#pragma unroll
        for (int j = 0; j < 4; j++)
#pragma unroll
            for (int e = 0; e < 4; e++) acc[i][j][e] = 0.f;

    int pro = KC < 3 ? KC : 3;
    for (int s = 0; s < pro; s++) { fill(s, s); CP_COMMIT(); }

    int arow = lane & 15, kh = (lane >> 4) * 8;
    int bn_ = ((lane >> 4) & 1) * 8 + (lane & 7), bk = ((lane >> 3) & 1) * 8;

    for (int kc = 0; kc < KC; kc++) {
        int s = kc & 3;
        int rem = KC - kc - 1;
        if (rem >= 2)      { CP_WAIT(2); }
        else if (rem == 1) { CP_WAIT(1); }
        else               { CP_WAIT(0); }
        __syncthreads();
        uint32_t abase = sbase + s * STG + (wm * 64) * 80;
        uint32_t bbase = sbase + s * STG + 10240 + (wn * 32) * 80;
#pragma unroll
        for (int ks = 0; ks < 2; ks++) {
            uint32_t bh[2][4];
#pragma unroll
            for (int g = 0; g < 2; g++) {
                uint32_t bd = bbase + (g*16 + bn_) * 80 + (ks*16 + bk) * 2;
                LDSM4(bh[g], bd);
            }
#pragma unroll
            for (int mt = 0; mt < 4; mt++) {
                uint32_t ah[4];
                uint32_t ad = abase + (mt*16 + arow) * 80 + (ks*16 + kh) * 2;
                LDSM4(ah, ad);
#pragma unroll
                for (int nt = 0; nt < 4; nt++) {
                    int g = nt >> 1, p = (nt & 1) * 2;
                    MMAF16(acc[mt][nt], ah, bh[g][p], bh[g][p+1]);
                }
            }
        }
        __syncthreads();
        if (kc + 3 < KC) { fill(kc + 3, (kc + 3) & 3); CP_COMMIT(); }
    }

    // epilogue: stage C in smem (pitch 132), stats + coalesced store
    float* cs = (float*)sm;
#pragma unroll
    for (int mt = 0; mt < 4; mt++)
#pragma unroll
        for (int nt = 0; nt < 4; nt++) {
            int r = wm*64 + mt*16 + (lane >> 2);
            int c = wn*32 + nt*8 + (lane & 3) * 2;
            *(float2*)(cs + r*132 + c)     = make_float2(acc[mt][nt][0], acc[mt][nt][1]);
            *(float2*)(cs + (r+8)*132 + c) = make_float2(acc[mt][nt][2], acc[mt][nt][3]);
        }
    __syncthreads();
    if (tid < 128 && n0 + tid < Nout) {
        float s = 0.f, q = 0.f;
#pragma unroll 8
        for (int r = 0; r < 128; r++) { float v = cs[r*132 + tid]; s += v; q = fmaf(v, v, q); }
        size_t ch = (size_t)z * Nout + n0 + tid;
        psum[ch * 128 + by] = s; psq[ch * 128 + by] = q;
    }
    float* C = Call + (size_t)z * MROWS * Nout;
#pragma unroll
    for (int i = 0; i < 16; i++) {
        int lin = tid + 256 * i;
        int r = lin >> 5, c4 = (lin & 31) * 4;
        if (n0 + c4 < Nout) {
            float4 v = *(float4*)(cs + r*132 + c4);
            *(float4*)(C + (size_t)(m0 + r) * Nout + n0 + c4) = v;
        }
    }
}

__global__ void bn_finalize(const float* __restrict__ psum, const float* __restrict__ psq,
                            const float* __restrict__ gam, const float* __restrict__ bet,
                            float* __restrict__ sc, float* __restrict__ sh, int total)
{
    int i = blockIdx.x * blockDim.x + threadIdx.x;
    if (i >= total) return;
    float s = 0.f, q = 0.f;
    const float* ps = psum + (size_t)i * 128;
    const float* pq = psq + (size_t)i * 128;
#pragma unroll 8
    for (int k = 0; k < 128; k++) { s += ps[k]; q += pq[k]; }
    float mean = s * (1.f / 16384.f);
    float var = fmaf(-mean, mean, q * (1.f / 16384.f));
    float g = gam[i] * rsqrtf(var + BN_EPS);
    sc[i] = g; sh[i] = fmaf(-mean, g, bet[i]);
}

// ----------------------------- softmax/pool (proven) ------------------------
__global__ void __launch_bounds__(256, 1)
softmax_pts_kernel(const float* __restrict__ t3, const float* __restrict__ h4raw,
                   const float* __restrict__ scaleL, const float* __restrict__ shiftL,
                   const float* __restrict__ aW4, const float* __restrict__ ab4,
                   float* __restrict__ out)
{
    int b = blockIdx.x, n = blockIdx.y;
    extern __shared__ float base_sh[];
    __shared__ float w4[3][64], b4[3];
    int tid = threadIdx.x;
    if (tid < 192) w4[tid / 64][tid % 64] = aW4[n * 192 + tid];
    if (tid < 3) b4[tid] = ab4[n * 3 + tid];
    const float* sc = scaleL + n * 64;
    const float* sh = shiftL + n * 64;
    const float* h4b = h4raw + ((size_t)n * MROWS + b * 512) * 64;
    for (int i = tid; i < 512 * 64; i += 256) {
        int l = i >> 6, k = i & 63;
        base_sh[l * 65 + k] = fmaxf(fmaf(h4b[i], sc[k], sh[k]), 0.f);
    }
    __syncthreads();
    int lane = tid & 31, warp = tid >> 5;
    const float* t3b = t3 + ((size_t)n * MROWS + b * 512) * 128;
    float* orow = out + ((size_t)b * 2048 + n * 128) * 3;
    for (int c = 0; c < 16; c++) {
        int m = warp + c * 8;
        float v[16], mx = -1e30f;
#pragma unroll
        for (int i = 0; i < 16; i++) { v[i] = t3b[(size_t)(lane + 32*i) * 128 + m]; mx = fmaxf(mx, v[i]); }
#pragma unroll
        for (int s = 16; s > 0; s >>= 1) mx = fmaxf(mx, __shfl_xor_sync(0xffffffffu, mx, s));
        float sum = 0.f;
#pragma unroll
        for (int i = 0; i < 16; i++) { v[i] = expf(v[i] - mx); sum += v[i]; }
#pragma unroll
        for (int s = 16; s > 0; s >>= 1) sum += __shfl_xor_sync(0xffffffffu, sum, s);
        float inv = 1.f / sum;
#pragma unroll
        for (int i = 0; i < 16; i++) v[i] *= inv;
        float o0 = 0.f, o1 = 0.f, o2 = 0.f;
        for (int k = 0; k < 64; k++) {
            float p = 0.f;
#pragma unroll
            for (int i = 0; i < 16; i++) p = fmaf(v[i], base_sh[(lane + 32*i) * 65 + k], p);
#pragma unroll
            for (int s = 16; s > 0; s >>= 1) p += __shfl_xor_sync(0xffffffffu, p, s);
            o0 = fmaf(w4[0][k], p, o0); o1 = fmaf(w4[1][k], p, o1); o2 = fmaf(w4[2][k], p, o2);
        }
        if (lane == 0) { orow[m*3] = o0 + b4[0]; orow[m*3+1] = o1 + b4[1]; orow[m*3+2] = o2 + b4[2]; }
    }
}

// ------------------------------- launch ------------------------------------
extern "C" void kernel_launch(void* const* d_in, const int* in_sizes, int n_in,
                              void* d_out, int out_size)
{
    (void)in_sizes; (void)n_in; (void)out_size;
    const float* x     = (const float*)d_in[0];
    const float* xpart = (const float*)d_in[1];
    const float* mW1 = (const float*)d_in[2];
    const float* mg1 = (const float*)d_in[4];
    const float* mB1 = (const float*)d_in[5];
    const float* mW2 = (const float*)d_in[6];
    const float* mg2 = (const float*)d_in[8];
    const float* mB2 = (const float*)d_in[9];
    const float* mW3 = (const float*)d_in[10];
    const float* mg3 = (const float*)d_in[12];
    const float* mB3 = (const float*)d_in[13];
    const float* mW4 = (const float*)d_in[14];
    const float* mg4 = (const float*)d_in[16];
    const float* mB4 = (const float*)d_in[17];
    const float* aW1 = (const float*)d_in[18];
    const float* ag1 = (const float*)d_in[20];
    const float* aB1 = (const float*)d_in[21];
    const float* aW2 = (const float*)d_in[22];
    const float* ag2 = (const float*)d_in[24];
    const float* aB2 = (const float*)d_in[25];
    const float* aW3 = (const float*)d_in[26];
    const float* aW4 = (const float*)d_in[28];
    const float* ab4 = (const float*)d_in[29];
    float* out = (float*)d_out;

    float *bufA, *bufB, *h4, *t1, *t2, *t3, *psum, *psq, *sc, *sh;
    __half *Af, *Xf, *W1f, *W2f, *W3f, *W4f, *B1f, *B2f, *B3f, *Wa1f, *Wa2f, *Wa3f;
    cudaGetSymbolAddress((void**)&bufA, g_bufA);
    cudaGetSymbolAddress((void**)&bufB, g_bufB);
    cudaGetSymbolAddress((void**)&h4, g_h4);
    cudaGetSymbolAddress((void**)&t1, g_t1);
    cudaGetSymbolAddress((void**)&t2, g_t2);
    cudaGetSymbolAddress((void**)&t3, g_t3);
    cudaGetSymbolAddress((void**)&psum, g_psum);
    cudaGetSymbolAddress((void**)&psq, g_psq);
    cudaGetSymbolAddress((void**)&sc, g_scale);
    cudaGetSymbolAddress((void**)&sh, g_shift);
    cudaGetSymbolAddress((void**)&Af, g_Af);
    cudaGetSymbolAddress((void**)&Xf, g_Xf);
    cudaGetSymbolAddress((void**)&W1f, g_W1f);
    cudaGetSymbolAddress((void**)&W2f, g_W2f);
    cudaGetSymbolAddress((void**)&W3f, g_W3f);
    cudaGetSymbolAddress((void**)&W4f, g_W4f);
    cudaGetSymbolAddress((void**)&B1f, g_B1f);
    cudaGetSymbolAddress((void**)&B2f, g_B2f);
    cudaGetSymbolAddress((void**)&B3f, g_B3f);
    cudaGetSymbolAddress((void**)&Wa1f, g_Wa1f);
    cudaGetSymbolAddress((void**)&Wa2f, g_Wa2f);
    cudaGetSymbolAddress((void**)&Wa3f, g_Wa3f);

    static bool init_done = false;
    static cudaStream_t s2;
    static cudaEvent_t evFork, evJoin;
    if (!init_done) {
        cudaFuncSetAttribute(softmax_pts_kernel, cudaFuncAttributeMaxDynamicSharedMemorySize, 512 * 65 * 4);
        cudaFuncSetAttribute(gemm_f16, cudaFuncAttributeMaxDynamicSharedMemorySize, 81920);
        cudaStreamCreateWithFlags(&s2, cudaStreamNonBlocking);
        cudaEventCreateWithFlags(&evFork, cudaEventDisableTiming);
        cudaEventCreateWithFlags(&evJoin, cudaEventDisableTiming);
        init_done = true;
    }

    const int SL = NBR * 512;
    const long MS512 = (long)MROWS * 512;
    const long MS64  = (long)MROWS * 64;
    const long MS128 = (long)MROWS * 128;

    cudaEventRecord(evFork, 0);
    cudaStreamWaitEvent(s2, evFork, 0);
    fps_kernel<<<32 * FPS_CL, 512, 0, s2>>>(xpart, out);
    cudaEventRecord(evJoin, s2);

    // weight + x conversions (fp16)
    conv_plain<<<(NBR*512*128)/256, 256>>>(mW1, W1f, NBR*512*128);
    conv_plain<<<(NBR*512*256)/256, 256>>>(mW2, W2f, NBR*512*256);
    conv_plain<<<(NBR*512*256)/256, 256>>>(mW3, W3f, NBR*512*256);
    conv_wpad_g<<<(NBR*128*512)/512, 256>>>(mW4, W4f, 512, 9);
    conv_wpad_g<<<(NBR*128*64)/512, 256>>>(aW1, Wa1f, 64, 6);
    conv_plain<<<(NBR*128*32)/256, 256>>>(aW2, Wa2f, NBR*128*32);
    conv_plain<<<(NBR*128*64)/256, 256>>>(aW3, Wa3f, NBR*128*64);
    conv_plain<<<(MROWS*128)/256, 256>>>(x, Xf, MROWS*128);

    // L1..L3
    gemm_f16<<<dim3(4, 128, NBR), 256, 81920>>>(Xf, W1f, bufA, psum, psq,
                                                256, 0, 512L*256, 512);
    bn_finalize<<<16, 256>>>(psum, psq, mg1, mB1, sc, sh, NBR * 512);

    conv_bn_g<<<(NBR*MROWS*512)/512, 256>>>(bufA, sc, sh, Af, 9);
    gemm_f16<<<dim3(4, 128, NBR), 256, 81920>>>(Af, W2f, bufB, psum, psq,
                                                512, MS512, 512L*512, 512);
    bn_finalize<<<16, 256>>>(psum, psq, mg2, mB2, sc + SL, sh + SL, NBR * 512);

    conv_bn_g<<<(NBR*MROWS*512)/512, 256>>>(bufB, sc + SL, sh + SL, Af, 9);
    gemm_f16<<<dim3(4, 128, NBR), 256, 81920>>>(Af, W3f, bufA, psum, psq,
                                                512, MS512, 512L*512, 512);
    bn_finalize<<<16, 256>>>(psum, psq, mg3, mB3, sc + 2 * SL, sh + 2 * SL, NBR * 512);

    // L4 (padded N)
    conv_bn_g<<<(NBR*MROWS*512)/512, 256>>>(bufA, sc + 2 * SL, sh + 2 * SL, Af, 9);
    gemm_f16<<<dim3(1, 128, NBR), 256, 81920>>>(Af, W4f, h4, psum, psq,
                                                512, MS512, 128L*512, 64);
    bn_finalize<<<2, 256>>>(psum, psq, mg4, mB4, sc + 3 * SL, sh + 3 * SL, NBR * 64);

    // A1: base = BN(h4) -> t1
    conv_bn_g<<<(NBR*MROWS*64)/512, 256>>>(h4, sc + 3 * SL, sh + 3 * SL, B1f, 6);
    gemm_f16<<<dim3(1, 128, NBR), 256, 81920>>>(B1f, Wa1f, t1, psum, psq,
                                                64, MS64, 128L*64, 64);
    bn_finalize<<<2, 256>>>(psum, psq, ag1, aB1, sc + 4 * SL, sh + 4 * SL, NBR * 64);

    // A2: BN(t1) -> t2
    conv_bn_g<<<(NBR*MROWS*64)/512, 256>>>(t1, sc + 4 * SL, sh + 4 * SL, B2f, 6);
    gemm_f16<<<dim3(1, 128, NBR), 256, 81920>>>(B2f, Wa2f, t2, psum, psq,
                                                64, MS64, 128L*64, 128);
    bn_finalize<<<4, 256>>>(psum, psq, ag2, aB2, sc + 5 * SL, sh + 5 * SL, NBR * 128);

    // A3: BN(t2) -> t3 logits
    conv_bn_g<<<(NBR*MROWS*128)/512, 256>>>(t2, sc + 5 * SL, sh + 5 * SL, B3f, 7);
    gemm_f16<<<dim3(1, 128, NBR), 256, 81920>>>(B3f, Wa3f, t3, psum, psq,
                                                128, MS128, 128L*128, 128);

    softmax_pts_kernel<<<dim3(32, NBR), 256, 512 * 65 * 4>>>(
        t3, h4, sc + 3 * SL, sh + 3 * SL, aW4, ab4, out);

    cudaStreamWaitEvent(0, evJoin, 0);
}

// round 13
// speedup vs baseline: 2.0277x; 1.0702x over previous
#include <cuda_runtime.h>
#include <cuda_fp16.h>
#include <cstdint>
#include <cstddef>

#define NBR 8
#define MROWS 16384
#define BN_EPS 1e-5f

// fp16 raw activation buffers
__device__ __align__(256) __half g_bufA[(size_t)NBR * MROWS * 512];
__device__ __align__(256) __half g_bufB[(size_t)NBR * MROWS * 512];
__device__ __align__(256) __half g_h4 [(size_t)NBR * MROWS * 64];
__device__ __align__(256) __half g_t1 [(size_t)NBR * MROWS * 64];
__device__ __align__(256) __half g_t2 [(size_t)NBR * MROWS * 128];
__device__ __align__(256) float  g_t3 [(size_t)NBR * MROWS * 128];
__device__ float g_psum [NBR * 512 * 128];
__device__ float g_psq  [NBR * 512 * 128];
__device__ float g_scale[6 * NBR * 512];
__device__ float g_shift[6 * NBR * 512];
// fp16 operand panels
__device__ __align__(16) __half g_Af [(size_t)NBR * MROWS * 512];
__device__ __align__(16) __half g_Xf [(size_t)MROWS * 256];
__device__ __align__(16) __half g_W1f[NBR * 512 * 256];
__device__ __align__(16) __half g_W2f[NBR * 512 * 512];
__device__ __align__(16) __half g_W3f[NBR * 512 * 512];
__device__ __align__(16) __half g_W4f[NBR * 128 * 512];
__device__ __align__(16) __half g_B1f[(size_t)NBR * MROWS * 64];
__device__ __align__(16) __half g_B2f[(size_t)NBR * MROWS * 64];
__device__ __align__(16) __half g_B3f[(size_t)NBR * MROWS * 128];
__device__ __align__(16) __half g_Wa1f[NBR * 128 * 64];
__device__ __align__(16) __half g_Wa2f[NBR * 128 * 64];
__device__ __align__(16) __half g_Wa3f[NBR * 128 * 128];

__device__ __forceinline__ uint32_t smem_u32(const void* p) {
    uint32_t a;
    asm("{ .reg .u64 t; cvta.to.shared.u64 t, %1; cvt.u32.u64 %0, t; }" : "=r"(a) : "l"(p));
    return a;
}
__device__ __forceinline__ void stc_f32(uint32_t sa, uint32_t rank, float v) {
    uint32_t r;
    asm volatile("mapa.shared::cluster.u32 %0, %1, %2;" : "=r"(r) : "r"(sa), "r"(rank));
    asm volatile("st.shared::cluster.f32 [%0], %1;" :: "r"(r), "f"(v) : "memory");
}
__device__ __forceinline__ void stc_u32(uint32_t sa, uint32_t rank, uint32_t v) {
    uint32_t r;
    asm volatile("mapa.shared::cluster.u32 %0, %1, %2;" : "=r"(r) : "r"(sa), "r"(rank));
    asm volatile("st.shared::cluster.u32 [%0], %1;" :: "r"(r), "r"(v) : "memory");
}
__device__ __forceinline__ void cpa16(uint32_t d, const void* g) {
    asm volatile("cp.async.cg.shared.global [%0], [%1], 16;" :: "r"(d), "l"(g));
}
#define CP_COMMIT() asm volatile("cp.async.commit_group;")
#define CP_WAIT(N)  asm volatile("cp.async.wait_group %0;" :: "n"(N))
#define LDSM4(R, ADDR) \
    asm volatile("ldmatrix.sync.aligned.m8n8.x4.shared.b16 {%0,%1,%2,%3}, [%4];" \
        : "=r"((R)[0]), "=r"((R)[1]), "=r"((R)[2]), "=r"((R)[3]) : "r"(ADDR))
#define MMAF16(D, A, B0, B1) \
    asm volatile("mma.sync.aligned.m16n8k16.row.col.f32.f16.f16.f32 " \
        "{%0,%1,%2,%3}, {%4,%5,%6,%7}, {%8,%9}, {%0,%1,%2,%3};" \
        : "+f"((D)[0]), "+f"((D)[1]), "+f"((D)[2]), "+f"((D)[3]) \
        : "r"((A)[0]), "r"((A)[1]), "r"((A)[2]), "r"((A)[3]), "r"(B0), "r"(B1))

// ------------------------------ FPS (proven) --------------------------------
#define FPS_CL 4
__global__ void __cluster_dims__(FPS_CL,1,1) __launch_bounds__(512,1)
fps_kernel(const float* __restrict__ xpart, float* __restrict__ out)
{
    uint32_t rank; asm("mov.u32 %0, %%cluster_ctarank;" : "=r"(rank));
    int b = blockIdx.x / FPS_CL;
    const float* xp = xpart + (size_t)b * 32768 * 3;
    int tid = threadIdx.x, lane = tid & 31, warp = tid >> 5;
    int pbase = (int)rank * 8192;
    float px[16], py[16], pz[16], dd[16];
#pragma unroll
    for (int i = 0; i < 16; i++) {
        int p = pbase + tid + 512 * i;
        px[i] = xp[p*3]; py[i] = xp[p*3+1]; pz[i] = xp[p*3+2]; dd[i] = 1e10f;
    }
    __shared__ float wv_[16]; __shared__ int wi_[16];
    __shared__ float wx_[16], wy_[16], wz_[16];
    __shared__ float cval[2][FPS_CL]; __shared__ int cidx[2][FPS_CL];
    __shared__ float cxx[2][FPS_CL], cyy[2][FPS_CL], czz[2][FPS_CL];
    float curx = xp[0], cury = xp[1], curz = xp[2];
    float* orow = out + ((size_t)b * 2048 + 1024) * 3;
    if (rank == 0 && tid == 0) { orow[0]=curx; orow[1]=cury; orow[2]=curz; }

    for (int t = 1; t < 1024; t++) {
        float bv = -1.f; int bi = 0x7fffffff;
        float bx = 0.f, by = 0.f, bz = 0.f;
#pragma unroll
        for (int i = 0; i < 16; i++) {
            float dx = __fsub_rn(px[i], curx), dy = __fsub_rn(py[i], cury), dz = __fsub_rn(pz[i], curz);
            float d = __fadd_rn(__fadd_rn(__fmul_rn(dx,dx), __fmul_rn(dy,dy)), __fmul_rn(dz,dz));
            dd[i] = fminf(dd[i], d);
            int gi = pbase + tid + 512 * i;
            if (dd[i] > bv || (dd[i] == bv && gi < bi)) { bv=dd[i]; bi=gi; bx=px[i]; by=py[i]; bz=pz[i]; }
        }
#pragma unroll
        for (int s = 16; s > 0; s >>= 1) {
            float ov = __shfl_down_sync(0xffffffffu, bv, s);
            int   oi = __shfl_down_sync(0xffffffffu, bi, s);
            float ox = __shfl_down_sync(0xffffffffu, bx, s);
            float oy = __shfl_down_sync(0xffffffffu, by, s);
            float oz = __shfl_down_sync(0xffffffffu, bz, s);
            if (ov > bv || (ov == bv && oi < bi)) { bv=ov; bi=oi; bx=ox; by=oy; bz=oz; }
        }
        if (lane == 0) { wv_[warp]=bv; wi_[warp]=bi; wx_[warp]=bx; wy_[warp]=by; wz_[warp]=bz; }
        __syncthreads();
        int par = t & 1;
        if (warp == 0) {
            bv = (lane < 16) ? wv_[lane] : -1.f;
            bi = (lane < 16) ? wi_[lane] : 0x7fffffff;
            bx = (lane < 16) ? wx_[lane] : 0.f;
            by = (lane < 16) ? wy_[lane] : 0.f;
            bz = (lane < 16) ? wz_[lane] : 0.f;
#pragma unroll
            for (int s = 8; s > 0; s >>= 1) {
                float ov = __shfl_down_sync(0xffffffffu, bv, s);
                int   oi = __shfl_down_sync(0xffffffffu, bi, s);
                float ox = __shfl_down_sync(0xffffffffu, bx, s);
                float oy = __shfl_down_sync(0xffffffffu, by, s);
                float oz = __shfl_down_sync(0xffffffffu, bz, s);
                if (ov > bv || (ov == bv && oi < bi)) { bv=ov; bi=oi; bx=ox; by=oy; bz=oz; }
            }
            if (lane == 0) {
                for (uint32_t r = 0; r < FPS_CL; r++) {
                    stc_f32(smem_u32(&cval[par][rank]), r, bv);
                    stc_u32(smem_u32(&cidx[par][rank]), r, (uint32_t)bi);
                    stc_f32(smem_u32(&cxx[par][rank]), r, bx);
                    stc_f32(smem_u32(&cyy[par][rank]), r, by);
                    stc_f32(smem_u32(&czz[par][rank]), r, bz);
                }
            }
        }
        asm volatile("barrier.cluster.arrive.aligned;" ::: "memory");
        asm volatile("barrier.cluster.wait.aligned;" ::: "memory");
        float vv = cval[par][0]; int vi = cidx[par][0];
        float nx = cxx[par][0], ny = cyy[par][0], nz = czz[par][0];
#pragma unroll
        for (int r = 1; r < FPS_CL; r++) {
            float ov = cval[par][r]; int oi = cidx[par][r];
            if (ov > vv || (ov == vv && oi < vi)) { vv=ov; vi=oi; nx=cxx[par][r]; ny=cyy[par][r]; nz=czz[par][r]; }
        }
        curx = nx; cury = ny; curz = nz;
        if (rank == 0 && tid == 0) { orow[t*3]=nx; orow[t*3+1]=ny; orow[t*3+2]=nz; }
    }
}

// ------------------------- fp16 conversion passes ---------------------------
__global__ void conv_plain(const float* __restrict__ S, __half* __restrict__ H, int nPairs)
{
    int p = blockIdx.x * 256 + threadIdx.x;
    if (p >= nPairs) return;
    float2 v = *(const float2*)(S + (size_t)p * 2);
    __half2 h; h.x = __float2half_rn(v.x); h.y = __float2half_rn(v.y);
    *(__half2*)(H + (size_t)p * 2) = h;
}
__global__ void conv_wpad_g(const float* __restrict__ S, __half* __restrict__ H, int K, int lk)
{
    int i2 = blockIdx.x * 256 + threadIdx.x;
    int idx = i2 * 2;
    int k = idx & (K - 1), n = (idx >> lk) & 127, z = idx >> (lk + 7);
    __half2 h;
    if (n < 64) {
        float2 v = *(const float2*)(S + ((size_t)z * 64 + n) * K + k);
        h.x = __float2half_rn(v.x); h.y = __float2half_rn(v.y);
    } else {
        h.x = h.y = __float2half_rn(0.f);
    }
    *(__half2*)(H + (size_t)idx) = h;
}
// BN+ReLU apply on fp16 raw -> fp16; 8 halves/thread; C = 1<<lc channels
__global__ void conv_bn_h(const __half* __restrict__ raw, const float* __restrict__ sc,
                          const float* __restrict__ sh, __half* __restrict__ H, int lc)
{
    size_t idx = ((size_t)blockIdx.x * 256 + threadIdx.x) * 8;
    int C = 1 << lc;
    int k = (int)(idx & (C - 1));
    int z = (int)(idx >> (lc + 14));
    uint4 rv = *(const uint4*)(raw + idx);
    const __half2* hp = (const __half2*)&rv;
    const float* scz = sc + z * C + k;
    const float* shz = sh + z * C + k;
    float4 s0 = *(const float4*)(scz), s1 = *(const float4*)(scz + 4);
    float4 t0 = *(const float4*)(shz), t1 = *(const float4*)(shz + 4);
    float sa[8] = {s0.x, s0.y, s0.z, s0.w, s1.x, s1.y, s1.z, s1.w};
    float ta[8] = {t0.x, t0.y, t0.z, t0.w, t1.x, t1.y, t1.z, t1.w};
    uint4 ov;
    __half2* op = (__half2*)&ov;
#pragma unroll
    for (int j = 0; j < 4; j++) {
        float f0 = __half2float(hp[j].x), f1 = __half2float(hp[j].y);
        float a0 = fmaxf(fmaf(f0, sa[2*j],   ta[2*j]),   0.f);
        float a1 = fmaxf(fmaf(f1, sa[2*j+1], ta[2*j+1]), 0.f);
        op[j].x = __float2half_rn(a0); op[j].y = __float2half_rn(a1);
    }
    *(uint4*)(H + idx) = ov;
}

// -------------- fp16 tensor-core GEMM, 4-stage cp.async, 2 CTAs/SM ---------
#define STG 20480
template<typename TOUT>
__global__ void __launch_bounds__(256, 2)
gemm_f16(const __half* __restrict__ Ag, const __half* __restrict__ Bg,
         TOUT* __restrict__ Call, float* __restrict__ psum, float* __restrict__ psq,
         int K, long aStride, long bStride, int Nout)
{
    extern __shared__ __align__(16) uint32_t sm[];
    int bx = blockIdx.x, by = blockIdx.y, z = blockIdx.z;
    int tid = threadIdx.x, lane = tid & 31, w = tid >> 5;
    int wm = w & 1, wn = w >> 1;
    int m0 = by * 128, n0 = bx * 128, KC = K >> 5;
    const __half* A = Ag + (size_t)z * aStride;
    const __half* B = Bg + (size_t)z * bStride;
    uint32_t sbase = smem_u32(sm);

    int lrow = tid & 127, pan = tid >> 7;
    const __half* Grow = (pan ? B + (size_t)(n0 + lrow) * K
                              : A + (size_t)(m0 + lrow) * K);
    uint32_t drow = (uint32_t)pan * 10240 + lrow * 80;

    auto fill = [&](int kc, int s) {
        uint32_t st = sbase + s * STG + drow;
        const __half* g = Grow + kc * 32;
        cpa16(st,      g);
        cpa16(st + 16, g + 8);
        cpa16(st + 32, g + 16);
        cpa16(st + 48, g + 24);
    };

    float acc[4][4][4];
#pragma unroll
    for (int i = 0; i < 4; i++)
#pragma unroll
        for (int j = 0; j < 4; j++)
#pragma unroll
            for (int e = 0; e < 4; e++) acc[i][j][e] = 0.f;

    int pro = KC < 3 ? KC : 3;
    for (int s = 0; s < pro; s++) { fill(s, s); CP_COMMIT(); }

    int arow = lane & 15, kh = (lane >> 4) * 8;
    int bn_ = ((lane >> 4) & 1) * 8 + (lane & 7), bk = ((lane >> 3) & 1) * 8;

    for (int kc = 0; kc < KC; kc++) {
        int s = kc & 3;
        int rem = KC - kc - 1;
        if (rem >= 2)      { CP_WAIT(2); }
        else if (rem == 1) { CP_WAIT(1); }
        else               { CP_WAIT(0); }
        __syncthreads();
        uint32_t abase = sbase + s * STG + (wm * 64) * 80;
        uint32_t bbase = sbase + s * STG + 10240 + (wn * 32) * 80;
#pragma unroll
        for (int ks = 0; ks < 2; ks++) {
            uint32_t bh[2][4];
#pragma unroll
            for (int g = 0; g < 2; g++) {
                uint32_t bd = bbase + (g*16 + bn_) * 80 + (ks*16 + bk) * 2;
                LDSM4(bh[g], bd);
            }
#pragma unroll
            for (int mt = 0; mt < 4; mt++) {
                uint32_t ah[4];
                uint32_t ad = abase + (mt*16 + arow) * 80 + (ks*16 + kh) * 2;
                LDSM4(ah, ad);
#pragma unroll
                for (int nt = 0; nt < 4; nt++) {
                    int g = nt >> 1, p = (nt & 1) * 2;
                    MMAF16(acc[mt][nt], ah, bh[g][p], bh[g][p+1]);
                }
            }
        }
        __syncthreads();
        if (kc + 3 < KC) { fill(kc + 3, (kc + 3) & 3); CP_COMMIT(); }
    }

    // epilogue: stage C in smem (pitch 132), stats + coalesced store
    float* cs = (float*)sm;
#pragma unroll
    for (int mt = 0; mt < 4; mt++)
#pragma unroll
        for (int nt = 0; nt < 4; nt++) {
            int r = wm*64 + mt*16 + (lane >> 2);
            int c = wn*32 + nt*8 + (lane & 3) * 2;
            *(float2*)(cs + r*132 + c)     = make_float2(acc[mt][nt][0], acc[mt][nt][1]);
            *(float2*)(cs + (r+8)*132 + c) = make_float2(acc[mt][nt][2], acc[mt][nt][3]);
        }
    __syncthreads();
    if (tid < 128 && n0 + tid < Nout) {
        float s = 0.f, q = 0.f;
#pragma unroll 8
        for (int r = 0; r < 128; r++) { float v = cs[r*132 + tid]; s += v; q = fmaf(v, v, q); }
        size_t ch = (size_t)z * Nout + n0 + tid;
        psum[ch * 128 + by] = s; psq[ch * 128 + by] = q;
    }
    TOUT* C = Call + (size_t)z * MROWS * Nout;
#pragma unroll
    for (int i = 0; i < 16; i++) {
        int lin = tid + 256 * i;
        int r = lin >> 5, c4 = (lin & 31) * 4;
        if (n0 + c4 < Nout) {
            float4 v = *(float4*)(cs + r*132 + c4);
            TOUT* dst = C + (size_t)(m0 + r) * Nout + n0 + c4;
            if constexpr (sizeof(TOUT) == 2) {
                __half2 h0, h1;
                h0.x = __float2half_rn(v.x); h0.y = __float2half_rn(v.y);
                h1.x = __float2half_rn(v.z); h1.y = __float2half_rn(v.w);
                uint32_t u0 = *(uint32_t*)&h0, u1 = *(uint32_t*)&h1;
                *(uint2*)dst = make_uint2(u0, u1);
            } else {
                *(float4*)dst = v;
            }
        }
    }
}

__global__ void bn_finalize(const float* __restrict__ psum, const float* __restrict__ psq,
                            const float* __restrict__ gam, const float* __restrict__ bet,
                            float* __restrict__ sc, float* __restrict__ sh, int total)
{
    int i = blockIdx.x * blockDim.x + threadIdx.x;
    if (i >= total) return;
    float s = 0.f, q = 0.f;
    const float* ps = psum + (size_t)i * 128;
    const float* pq = psq + (size_t)i * 128;
#pragma unroll 8
    for (int k = 0; k < 128; k++) { s += ps[k]; q += pq[k]; }
    float mean = s * (1.f / 16384.f);
    float var = fmaf(-mean, mean, q * (1.f / 16384.f));
    float g = gam[i] * rsqrtf(var + BN_EPS);
    sc[i] = g; sh[i] = fmaf(-mean, g, bet[i]);
}

// ----------------------------- softmax/pool ---------------------------------
__global__ void __launch_bounds__(256, 1)
softmax_pts_kernel(const float* __restrict__ t3, const __half* __restrict__ h4raw,
                   const float* __restrict__ scaleL, const float* __restrict__ shiftL,
                   const float* __restrict__ aW4, const float* __restrict__ ab4,
                   float* __restrict__ out)
{
    int b = blockIdx.x, n = blockIdx.y;
    extern __shared__ float base_sh[];
    __shared__ float w4[3][64], b4[3];
    int tid = threadIdx.x;
    if (tid < 192) w4[tid / 64][tid % 64] = aW4[n * 192 + tid];
    if (tid < 3) b4[tid] = ab4[n * 3 + tid];
    const float* sc = scaleL + n * 64;
    const float* sh = shiftL + n * 64;
    const __half* h4b = h4raw + ((size_t)n * MROWS + b * 512) * 64;
    for (int i = tid; i < 512 * 64; i += 256) {
        int l = i >> 6, k = i & 63;
        base_sh[l * 65 + k] = fmaxf(fmaf(__half2float(h4b[i]), sc[k], sh[k]), 0.f);
    }
    __syncthreads();
    int lane = tid & 31, warp = tid >> 5;
    const float* t3b = t3 + ((size_t)n * MROWS + b * 512) * 128;
    float* orow = out + ((size_t)b * 2048 + n * 128) * 3;
    for (int c = 0; c < 16; c++) {
        int m = warp + c * 8;
        float v[16], mx = -1e30f;
#pragma unroll
        for (int i = 0; i < 16; i++) { v[i] = t3b[(size_t)(lane + 32*i) * 128 + m]; mx = fmaxf(mx, v[i]); }
#pragma unroll
        for (int s = 16; s > 0; s >>= 1) mx = fmaxf(mx, __shfl_xor_sync(0xffffffffu, mx, s));
        float sum = 0.f;
#pragma unroll
        for (int i = 0; i < 16; i++) { v[i] = expf(v[i] - mx); sum += v[i]; }
#pragma unroll
        for (int s = 16; s > 0; s >>= 1) sum += __shfl_xor_sync(0xffffffffu, sum, s);
        float inv = 1.f / sum;
#pragma unroll
        for (int i = 0; i < 16; i++) v[i] *= inv;
        float o0 = 0.f, o1 = 0.f, o2 = 0.f;
        for (int k = 0; k < 64; k++) {
            float p = 0.f;
#pragma unroll
            for (int i = 0; i < 16; i++) p = fmaf(v[i], base_sh[(lane + 32*i) * 65 + k], p);
#pragma unroll
            for (int s = 16; s > 0; s >>= 1) p += __shfl_xor_sync(0xffffffffu, p, s);
            o0 = fmaf(w4[0][k], p, o0); o1 = fmaf(w4[1][k], p, o1); o2 = fmaf(w4[2][k], p, o2);
        }
        if (lane == 0) { orow[m*3] = o0 + b4[0]; orow[m*3+1] = o1 + b4[1]; orow[m*3+2] = o2 + b4[2]; }
    }
}

// ------------------------------- launch ------------------------------------
extern "C" void kernel_launch(void* const* d_in, const int* in_sizes, int n_in,
                              void* d_out, int out_size)
{
    (void)in_sizes; (void)n_in; (void)out_size;
    const float* x     = (const float*)d_in[0];
    const float* xpart = (const float*)d_in[1];
    const float* mW1 = (const float*)d_in[2];
    const float* mg1 = (const float*)d_in[4];
    const float* mB1 = (const float*)d_in[5];
    const float* mW2 = (const float*)d_in[6];
    const float* mg2 = (const float*)d_in[8];
    const float* mB2 = (const float*)d_in[9];
    const float* mW3 = (const float*)d_in[10];
    const float* mg3 = (const float*)d_in[12];
    const float* mB3 = (const float*)d_in[13];
    const float* mW4 = (const float*)d_in[14];
    const float* mg4 = (const float*)d_in[16];
    const float* mB4 = (const float*)d_in[17];
    const float* aW1 = (const float*)d_in[18];
    const float* ag1 = (const float*)d_in[20];
    const float* aB1 = (const float*)d_in[21];
    const float* aW2 = (const float*)d_in[22];
    const float* ag2 = (const float*)d_in[24];
    const float* aB2 = (const float*)d_in[25];
    const float* aW3 = (const float*)d_in[26];
    const float* aW4 = (const float*)d_in[28];
    const float* ab4 = (const float*)d_in[29];
    float* out = (float*)d_out;

    __half *bufA, *bufB, *h4, *t1, *t2;
    float *t3, *psum, *psq, *sc, *sh;
    __half *Af, *Xf, *W1f, *W2f, *W3f, *W4f, *B1f, *B2f, *B3f, *Wa1f, *Wa2f, *Wa3f;
    cudaGetSymbolAddress((void**)&bufA, g_bufA);
    cudaGetSymbolAddress((void**)&bufB, g_bufB);
    cudaGetSymbolAddress((void**)&h4, g_h4);
    cudaGetSymbolAddress((void**)&t1, g_t1);
    cudaGetSymbolAddress((void**)&t2, g_t2);
    cudaGetSymbolAddress((void**)&t3, g_t3);
    cudaGetSymbolAddress((void**)&psum, g_psum);
    cudaGetSymbolAddress((void**)&psq, g_psq);
    cudaGetSymbolAddress((void**)&sc, g_scale);
    cudaGetSymbolAddress((void**)&sh, g_shift);
    cudaGetSymbolAddress((void**)&Af, g_Af);
    cudaGetSymbolAddress((void**)&Xf, g_Xf);
    cudaGetSymbolAddress((void**)&W1f, g_W1f);
    cudaGetSymbolAddress((void**)&W2f, g_W2f);
    cudaGetSymbolAddress((void**)&W3f, g_W3f);
    cudaGetSymbolAddress((void**)&W4f, g_W4f);
    cudaGetSymbolAddress((void**)&B1f, g_B1f);
    cudaGetSymbolAddress((void**)&B2f, g_B2f);
    cudaGetSymbolAddress((void**)&B3f, g_B3f);
    cudaGetSymbolAddress((void**)&Wa1f, g_Wa1f);
    cudaGetSymbolAddress((void**)&Wa2f, g_Wa2f);
    cudaGetSymbolAddress((void**)&Wa3f, g_Wa3f);

    static bool init_done = false;
    static cudaStream_t s2;
    static cudaEvent_t evFork, evJoin;
    if (!init_done) {
        cudaFuncSetAttribute(softmax_pts_kernel, cudaFuncAttributeMaxDynamicSharedMemorySize, 512 * 65 * 4);
        cudaFuncSetAttribute(gemm_f16<__half>, cudaFuncAttributeMaxDynamicSharedMemorySize, 81920);
        cudaFuncSetAttribute(gemm_f16<float>,  cudaFuncAttributeMaxDynamicSharedMemorySize, 81920);
        cudaStreamCreateWithFlags(&s2, cudaStreamNonBlocking);
        cudaEventCreateWithFlags(&evFork, cudaEventDisableTiming);
        cudaEventCreateWithFlags(&evJoin, cudaEventDisableTiming);
        init_done = true;
    }

    const int SL = NBR * 512;
    const long MS512 = (long)MROWS * 512;
    const long MS64  = (long)MROWS * 64;
    const long MS128 = (long)MROWS * 128;

    cudaEventRecord(evFork, 0);
    cudaStreamWaitEvent(s2, evFork, 0);
    fps_kernel<<<32 * FPS_CL, 512, 0, s2>>>(xpart, out);
    cudaEventRecord(evJoin, s2);

    // weight + x conversions (fp16)
    conv_plain<<<(NBR*512*128)/256, 256>>>(mW1, W1f, NBR*512*128);
    conv_plain<<<(NBR*512*256)/256, 256>>>(mW2, W2f, NBR*512*256);
    conv_plain<<<(NBR*512*256)/256, 256>>>(mW3, W3f, NBR*512*256);
    conv_wpad_g<<<(NBR*128*512)/512, 256>>>(mW4, W4f, 512, 9);
    conv_wpad_g<<<(NBR*128*64)/512, 256>>>(aW1, Wa1f, 64, 6);
    conv_plain<<<(NBR*128*32)/256, 256>>>(aW2, Wa2f, NBR*128*32);
    conv_plain<<<(NBR*128*64)/256, 256>>>(aW3, Wa3f, NBR*128*64);
    conv_plain<<<(MROWS*128)/256, 256>>>(x, Xf, MROWS*128);

    // L1..L3 (fp16 raw out)
    gemm_f16<__half><<<dim3(4, 128, NBR), 256, 81920>>>(Xf, W1f, bufA, psum, psq,
                                                        256, 0, 512L*256, 512);
    bn_finalize<<<16, 256>>>(psum, psq, mg1, mB1, sc, sh, NBR * 512);

    conv_bn_h<<<(NBR*MROWS*512)/2048, 256>>>(bufA, sc, sh, Af, 9);
    gemm_f16<__half><<<dim3(4, 128, NBR), 256, 81920>>>(Af, W2f, bufB, psum, psq,
                                                        512, MS512, 512L*512, 512);
    bn_finalize<<<16, 256>>>(psum, psq, mg2, mB2, sc + SL, sh + SL, NBR * 512);

    conv_bn_h<<<(NBR*MROWS*512)/2048, 256>>>(bufB, sc + SL, sh + SL, Af, 9);
    gemm_f16<__half><<<dim3(4, 128, NBR), 256, 81920>>>(Af, W3f, bufA, psum, psq,
                                                        512, MS512, 512L*512, 512);
    bn_finalize<<<16, 256>>>(psum, psq, mg3, mB3, sc + 2 * SL, sh + 2 * SL, NBR * 512);

    // L4 (padded N, fp16 raw out)
    conv_bn_h<<<(NBR*MROWS*512)/2048, 256>>>(bufA, sc + 2 * SL, sh + 2 * SL, Af, 9);
    gemm_f16<__half><<<dim3(1, 128, NBR), 256, 81920>>>(Af, W4f, h4, psum, psq,
                                                        512, MS512, 128L*512, 64);
    bn_finalize<<<2, 256>>>(psum, psq, mg4, mB4, sc + 3 * SL, sh + 3 * SL, NBR * 64);

    // A1: base = BN(h4) -> t1 (fp16 raw)
    conv_bn_h<<<(NBR*MROWS*64)/2048, 256>>>(h4, sc + 3 * SL, sh + 3 * SL, B1f, 6);
    gemm_f16<__half><<<dim3(1, 128, NBR), 256, 81920>>>(B1f, Wa1f, t1, psum, psq,
                                                        64, MS64, 128L*64, 64);
    bn_finalize<<<2, 256>>>(psum, psq, ag1, aB1, sc + 4 * SL, sh + 4 * SL, NBR * 64);

    // A2: BN(t1) -> t2 (fp16 raw)
    conv_bn_h<<<(NBR*MROWS*64)/2048, 256>>>(t1, sc + 4 * SL, sh + 4 * SL, B2f, 6);
    gemm_f16<__half><<<dim3(1, 128, NBR), 256, 81920>>>(B2f, Wa2f, t2, psum, psq,
                                                        64, MS64, 128L*64, 128);
    bn_finalize<<<4, 256>>>(psum, psq, ag2, aB2, sc + 5 * SL, sh + 5 * SL, NBR * 128);

    // A3: BN(t2) -> t3 logits (fp32 for softmax)
    conv_bn_h<<<(NBR*MROWS*128)/2048, 256>>>(t2, sc + 5 * SL, sh + 5 * SL, B3f, 7);
    gemm_f16<float><<<dim3(1, 128, NBR), 256, 81920>>>(B3f, Wa3f, t3, psum, psq,
                                                       128, MS128, 128L*128, 128);

    softmax_pts_kernel<<<dim3(32, NBR), 256, 512 * 65 * 4>>>(
        t3, h4, sc + 3 * SL, sh + 3 * SL, aW4, ab4, out);

    cudaStreamWaitEvent(0, evJoin, 0);
}